// round 2
// baseline (speedup 1.0000x reference)
#include <cuda_runtime.h>
#include <math.h>

// Problem constants
#define CB   4
#define CS   1024
#define CD   1024
#define CH   16
#define CHD  64
#define CL   6
#define COUT 512
#define CM   (CB*CS)   // 4096 rows in the flattened [B*S, D] activation

// ---------------- scratch (device globals; no allocation allowed) ----------
__device__ float g_h [CM*CD];   // residual stream
__device__ float g_hn[CM*CD];   // normalized activations
__device__ float g_q [CM*CD];
__device__ float g_k [CM*CD];
__device__ float g_v [CM*CD];
__device__ float g_at[CM*CD];   // attention output (combined heads)
__device__ float g_sc[(size_t)CB*CH*CS*CS];  // scores/probs, 256 MB

// ---------------- h = x + pe ------------------------------------------------
__global__ void __launch_bounds__(256) k_addpe(const float* __restrict__ x,
                                               const float* __restrict__ pe) {
    const int D4 = CD / 4;
    int i = blockIdx.x * 256 + threadIdx.x;           // over CM*CD/4 float4s
    float4 a = reinterpret_cast<const float4*>(x)[i];
    int row = i / D4;                                  // b*S + s
    int pei = (row & (CS - 1)) * D4 + (i - row * D4);
    float4 p = reinterpret_cast<const float4*>(pe)[pei];
    a.x += p.x; a.y += p.y; a.z += p.z; a.w += p.w;
    reinterpret_cast<float4*>(g_h)[i] = a;
}

// ---------------- LayerNorm over last dim (1024), one block per row ---------
__global__ void __launch_bounds__(256) k_ln(const float* __restrict__ in,
                                            float* __restrict__ out,
                                            const float* __restrict__ gw,
                                            const float* __restrict__ bw) {
    __shared__ float s_s[8], s_q[8];
    const int row = blockIdx.x;
    const int t = threadIdx.x;
    float4 v = reinterpret_cast<const float4*>(in + (size_t)row * CD)[t];
    float s  = v.x + v.y + v.z + v.w;
    float q2 = v.x*v.x + v.y*v.y + v.z*v.z + v.w*v.w;
#pragma unroll
    for (int o = 16; o; o >>= 1) {
        s  += __shfl_xor_sync(0xffffffffu, s,  o);
        q2 += __shfl_xor_sync(0xffffffffu, q2, o);
    }
    if ((t & 31) == 0) { s_s[t >> 5] = s; s_q[t >> 5] = q2; }
    __syncthreads();
    if (t == 0) {
        float a = 0.f, b2 = 0.f;
#pragma unroll
        for (int w = 0; w < 8; w++) { a += s_s[w]; b2 += s_q[w]; }
        s_s[0] = a; s_q[0] = b2;
    }
    __syncthreads();
    const float mu  = s_s[0] * (1.0f / CD);
    const float var = s_q[0] * (1.0f / CD) - mu * mu;
    const float inv = rsqrtf(var + 1e-5f);
    float4 g4 = reinterpret_cast<const float4*>(gw)[t];
    float4 b4 = reinterpret_cast<const float4*>(bw)[t];
    float4 o4;
    o4.x = (v.x - mu) * inv * g4.x + b4.x;
    o4.y = (v.y - mu) * inv * g4.y + b4.y;
    o4.z = (v.z - mu) * inv * g4.z + b4.z;
    o4.w = (v.w - mu) * inv * g4.w + b4.w;
    reinterpret_cast<float4*>(out + (size_t)row * CD)[t] = o4;
}

// ---------------- SGEMM: C[M,N] = A[M,K] * B[N,K]^T (+ optional residual) ---
// 128x128x16 tile, 256 threads, 8x8 micro-tile per thread.
__global__ void __launch_bounds__(256) k_gemm(const float* __restrict__ A,
                                              const float* __restrict__ B,
                                              const float* Res, float* C,
                                              int N, int K, int addRes) {
    __shared__ float As[16][132];
    __shared__ float Bs[16][132];
    const int tid  = threadIdx.x;
    const int brow = blockIdx.y << 7;
    const int bcol = blockIdx.x << 7;
    const int tr = (tid >> 4) << 3;     // output row offset within tile
    const int tc = (tid & 15) << 3;     // output col offset within tile
    const int lr = tid >> 2;            // load row (0..63)
    const int lc = (tid & 3) << 2;      // load col group (0,4,8,12)

    float acc[8][8] = {};

    const float* Ap = A + (size_t)(brow + lr) * K + lc;
    const float* Bp = B + (size_t)(bcol + lr) * K + lc;

    for (int k0 = 0; k0 < K; k0 += 16) {
#pragma unroll
        for (int i = 0; i < 2; i++) {
            float4 va = *reinterpret_cast<const float4*>(Ap + (size_t)(i*64) * K + k0);
            As[lc+0][lr+i*64] = va.x; As[lc+1][lr+i*64] = va.y;
            As[lc+2][lr+i*64] = va.z; As[lc+3][lr+i*64] = va.w;
            float4 vb = *reinterpret_cast<const float4*>(Bp + (size_t)(i*64) * K + k0);
            Bs[lc+0][lr+i*64] = vb.x; Bs[lc+1][lr+i*64] = vb.y;
            Bs[lc+2][lr+i*64] = vb.z; Bs[lc+3][lr+i*64] = vb.w;
        }
        __syncthreads();
#pragma unroll
        for (int kk = 0; kk < 16; kk++) {
            float a[8], b[8];
            *reinterpret_cast<float4*>(&a[0]) = *reinterpret_cast<const float4*>(&As[kk][tr]);
            *reinterpret_cast<float4*>(&a[4]) = *reinterpret_cast<const float4*>(&As[kk][tr+4]);
            *reinterpret_cast<float4*>(&b[0]) = *reinterpret_cast<const float4*>(&Bs[kk][tc]);
            *reinterpret_cast<float4*>(&b[4]) = *reinterpret_cast<const float4*>(&Bs[kk][tc+4]);
#pragma unroll
            for (int i = 0; i < 8; i++)
#pragma unroll
                for (int j = 0; j < 8; j++)
                    acc[i][j] = fmaf(a[i], b[j], acc[i][j]);
        }
        __syncthreads();
    }

#pragma unroll
    for (int i = 0; i < 8; i++) {
        float* Cp = C + (size_t)(brow + tr + i) * N + bcol + tc;
        float4 o0 = make_float4(acc[i][0], acc[i][1], acc[i][2], acc[i][3]);
        float4 o1 = make_float4(acc[i][4], acc[i][5], acc[i][6], acc[i][7]);
        if (addRes) {
            const float* Rp = Res + (size_t)(brow + tr + i) * N + bcol + tc;
            float4 r0 = *reinterpret_cast<const float4*>(Rp);
            float4 r1 = *reinterpret_cast<const float4*>(Rp + 4);
            o0.x += r0.x; o0.y += r0.y; o0.z += r0.z; o0.w += r0.w;
            o1.x += r1.x; o1.y += r1.y; o1.z += r1.z; o1.w += r1.w;
        }
        *reinterpret_cast<float4*>(Cp)     = o0;
        *reinterpret_cast<float4*>(Cp + 4) = o1;
    }
}

// ---------------- scores = (Q . K^T) * scale, lower-triangular tiles only ---
// Grid: (kb=16, qb=16, bh=64). 64x64 output tile, K=64 (head dim), 4x4/thread.
__global__ void __launch_bounds__(256) k_scores() {
    const int kb = blockIdx.x, qb = blockIdx.y;
    if (kb > qb) return;
    const int bh = blockIdx.z;
    const int b = bh >> 4, h = bh & 15;
    __shared__ float Qs[64][68];   // transposed: Qs[d][q]
    __shared__ float Ks[64][68];   // transposed: Ks[d][k]
    const int tid = threadIdx.x;
    const int r0 = tid >> 4;            // 0..15
    const int c0 = (tid & 15) << 2;     // 0..60

    const float* Qg = g_q + ((size_t)(b*CS + qb*64 + r0)) * CD + h*64 + c0;
    const float* Kg = g_k + ((size_t)(b*CS + kb*64 + r0)) * CD + h*64 + c0;
#pragma unroll
    for (int i = 0; i < 4; i++) {
        float4 vq = *reinterpret_cast<const float4*>(Qg + (size_t)(i*16) * CD);
        Qs[c0+0][r0+i*16] = vq.x; Qs[c0+1][r0+i*16] = vq.y;
        Qs[c0+2][r0+i*16] = vq.z; Qs[c0+3][r0+i*16] = vq.w;
        float4 vk = *reinterpret_cast<const float4*>(Kg + (size_t)(i*16) * CD);
        Ks[c0+0][r0+i*16] = vk.x; Ks[c0+1][r0+i*16] = vk.y;
        Ks[c0+2][r0+i*16] = vk.z; Ks[c0+3][r0+i*16] = vk.w;
    }
    __syncthreads();

    const int tq = (tid >> 4) << 2;
    const int tk = (tid & 15) << 2;
    float acc[4][4] = {};
#pragma unroll
    for (int d = 0; d < 64; d++) {
        float a[4], b4[4];
        *reinterpret_cast<float4*>(a)  = *reinterpret_cast<const float4*>(&Qs[d][tq]);
        *reinterpret_cast<float4*>(b4) = *reinterpret_cast<const float4*>(&Ks[d][tk]);
#pragma unroll
        for (int i = 0; i < 4; i++)
#pragma unroll
            for (int j = 0; j < 4; j++)
                acc[i][j] = fmaf(a[i], b4[j], acc[i][j]);
    }
    const float scale = 0.125f;   // 1/sqrt(64)
    float* Sg = g_sc + ((size_t)bh * CS + qb*64 + tq) * CS + kb*64 + tk;
#pragma unroll
    for (int i = 0; i < 4; i++) {
        float4 o = make_float4(acc[i][0]*scale, acc[i][1]*scale,
                               acc[i][2]*scale, acc[i][3]*scale);
        *reinterpret_cast<float4*>(Sg + (size_t)i * CS) = o;
    }
}

// ---------------- causal softmax over row q (reads k<=q, zero-fills tile) ---
__global__ void __launch_bounds__(128) k_softmax() {
    __shared__ float smax[4], ssum[4];
    const size_t row = blockIdx.x;          // bh*1024 + q
    const int q = blockIdx.x & (CS - 1);
    float* p = g_sc + row * CS;
    const int n = q + 1;
    const int t = threadIdx.x;

    float m = -1e30f;
    for (int k = t; k < n; k += 128) m = fmaxf(m, p[k]);
#pragma unroll
    for (int o = 16; o; o >>= 1) m = fmaxf(m, __shfl_xor_sync(0xffffffffu, m, o));
    if ((t & 31) == 0) smax[t >> 5] = m;
    __syncthreads();
    m = fmaxf(fmaxf(smax[0], smax[1]), fmaxf(smax[2], smax[3]));

    float s = 0.f;
    for (int k = t; k < n; k += 128) { float e = __expf(p[k] - m); p[k] = e; s += e; }
#pragma unroll
    for (int o = 16; o; o >>= 1) s += __shfl_xor_sync(0xffffffffu, s, o);
    if ((t & 31) == 0) ssum[t >> 5] = s;
    __syncthreads();
    s = ssum[0] + ssum[1] + ssum[2] + ssum[3];
    const float inv = 1.0f / s;
    for (int k = t; k < n; k += 128) p[k] *= inv;

    // zero the masked remainder of the diagonal 64-tile so PV can read it
    const int kend = ((q >> 6) + 1) << 6;
    for (int k = n + t; k < kend; k += 128) p[k] = 0.f;
}

// ---------------- attn = P . V  (causal: kb <= qb) ---------------------------
// Grid: (qb=16, bh=64). Output tile 64(q) x 64(hd), 4x4/thread.
__global__ void __launch_bounds__(256) k_attnv() {
    const int qb = blockIdx.x;
    const int bh = blockIdx.y;
    const int b = bh >> 4, h = bh & 15;
    __shared__ float Ps[64][68];   // transposed: Ps[k][q]
    __shared__ float Vs[64][68];   // natural:    Vs[k][hd]
    const int tid = threadIdx.x;
    const int r0 = tid >> 4;
    const int c0 = (tid & 15) << 2;
    const int tq = (tid >> 4) << 2;
    const int th = (tid & 15) << 2;
    float acc[4][4] = {};

    const float* Pg = g_sc + ((size_t)bh * CS + qb*64 + r0) * CS + c0;
    const float* Vg = g_v + ((size_t)(b*CS + r0)) * CD + h*64 + c0;

    for (int kb = 0; kb <= qb; kb++) {
#pragma unroll
        for (int i = 0; i < 4; i++) {
            float4 vp = *reinterpret_cast<const float4*>(Pg + (size_t)(i*16) * CS + kb*64);
            Ps[c0+0][r0+i*16] = vp.x; Ps[c0+1][r0+i*16] = vp.y;
            Ps[c0+2][r0+i*16] = vp.z; Ps[c0+3][r0+i*16] = vp.w;
            float4 vv = *reinterpret_cast<const float4*>(Vg + (size_t)(kb*64 + i*16) * CD);
            *reinterpret_cast<float4*>(&Vs[r0+i*16][c0]) = vv;
        }
        __syncthreads();
#pragma unroll
        for (int k = 0; k < 64; k++) {
            float a[4], v4[4];
            *reinterpret_cast<float4*>(a)  = *reinterpret_cast<const float4*>(&Ps[k][tq]);
            *reinterpret_cast<float4*>(v4) = *reinterpret_cast<const float4*>(&Vs[k][th]);
#pragma unroll
            for (int i = 0; i < 4; i++)
#pragma unroll
                for (int j = 0; j < 4; j++)
                    acc[i][j] = fmaf(a[i], v4[j], acc[i][j]);
        }
        __syncthreads();
    }

    float* Og = g_at + ((size_t)(b*CS + qb*64 + tq)) * CD + h*64 + th;
#pragma unroll
    for (int i = 0; i < 4; i++) {
        float4 o = make_float4(acc[i][0], acc[i][1], acc[i][2], acc[i][3]);
        *reinterpret_cast<float4*>(Og + (size_t)i * CD) = o;
    }
}

// ---------------- launch -----------------------------------------------------
extern "C" void kernel_launch(void* const* d_in, const int* in_sizes, int n_in,
                              void* d_out, int out_size) {
    const float* x    = (const float*)d_in[0];
    const float* pe   = (const float*)d_in[1];
    // d_in[2] = mask (unused; causality handled analytically)
    const float* ln1g = (const float*)d_in[3];
    const float* ln1b = (const float*)d_in[4];
    const float* wq   = (const float*)d_in[5];
    const float* wk   = (const float*)d_in[6];
    const float* wv   = (const float*)d_in[7];
    const float* wo   = (const float*)d_in[8];
    const float* ln2g = (const float*)d_in[9];
    const float* ln2b = (const float*)d_in[10];
    const float* wf   = (const float*)d_in[11];
    const float* lnfg = (const float*)d_in[12];
    const float* lnfb = (const float*)d_in[13];
    const float* wout = (const float*)d_in[14];

    float *ph, *phn, *pq, *pk, *pv, *pat;
    cudaGetSymbolAddress((void**)&ph,  g_h);
    cudaGetSymbolAddress((void**)&phn, g_hn);
    cudaGetSymbolAddress((void**)&pq,  g_q);
    cudaGetSymbolAddress((void**)&pk,  g_k);
    cudaGetSymbolAddress((void**)&pv,  g_v);
    cudaGetSymbolAddress((void**)&pat, g_at);

    k_addpe<<<(CM * CD / 4) / 256, 256>>>(x, pe);

    const dim3 gProj(CD / 128, CM / 128);    // (8, 32)
    const dim3 gOut (COUT / 128, CM / 128);  // (4, 32)
    const dim3 gSc  (CS / 64, CS / 64, CB * CH);
    const dim3 gAv  (CS / 64, CB * CH);

    for (int l = 0; l < CL; l++) {
        const size_t od  = (size_t)l * CD;
        const size_t odd = (size_t)l * CD * CD;
        k_ln<<<CM, 256>>>(ph, phn, ln1g + od, ln1b + od);
        k_gemm<<<gProj, 256>>>(phn, wq + odd, nullptr, pq, CD, CD, 0);
        k_gemm<<<gProj, 256>>>(phn, wk + odd, nullptr, pk, CD, CD, 0);
        k_gemm<<<gProj, 256>>>(phn, wv + odd, nullptr, pv, CD, CD, 0);
        k_scores<<<gSc, 256>>>();
        k_softmax<<<CB * CH * CS, 128>>>();
        k_attnv<<<gAv, 256>>>();
        k_gemm<<<gProj, 256>>>(pat, wo + odd, ph, ph, CD, CD, 1);
        k_ln<<<CM, 256>>>(ph, phn, ln2g + od, ln2b + od);
        k_gemm<<<gProj, 256>>>(phn, wf + odd, ph, ph, CD, CD, 1);
    }
    k_ln<<<CM, 256>>>(ph, phn, lnfg, lnfb);
    k_gemm<<<gOut, 256>>>(phn, wout, nullptr, (float*)d_out, COUT, CD, 0);
}

// round 3
// speedup vs baseline: 2.3802x; 2.3802x over previous
#include <cuda_runtime.h>
#include <math.h>
#include <stdint.h>

// Problem constants
#define CB   4
#define CS   1024
#define CD   1024
#define CH   16
#define CHD  64
#define CL   6
#define COUT 512
#define CM   (CB*CS)   // 4096 rows in the flattened [B*S, D] activation

// ---------------- scratch (device globals; no allocation allowed) ----------
__device__ float g_h [CM*CD];   // residual stream
__device__ float g_hn[CM*CD];   // normalized activations
__device__ float g_q [CM*CD];
__device__ float g_k [CM*CD];
__device__ float g_v [CM*CD];
__device__ float g_at[CM*CD];   // attention output (combined heads)
__device__ float g_sc[(size_t)CB*CH*CS*CS];  // scores/probs, 256 MB

// ---------------- helpers ----------------------------------------------------
__device__ __forceinline__ uint32_t f2tf(float f) {
    uint32_t u;
    asm("cvt.rna.tf32.f32 %0, %1;" : "=r"(u) : "f"(f));
    return u;
}

__device__ __forceinline__ void mma_tf32(float* c, const uint32_t* a, const uint32_t* b) {
    asm volatile(
        "mma.sync.aligned.m16n8k8.row.col.f32.tf32.tf32.f32 "
        "{%0,%1,%2,%3}, {%4,%5,%6,%7}, {%8,%9}, {%0,%1,%2,%3};\n"
        : "+f"(c[0]), "+f"(c[1]), "+f"(c[2]), "+f"(c[3])
        : "r"(a[0]), "r"(a[1]), "r"(a[2]), "r"(a[3]),
          "r"(b[0]), "r"(b[1]));
}

// ---------------- h = x + pe ------------------------------------------------
__global__ void __launch_bounds__(256) k_addpe(const float* __restrict__ x,
                                               const float* __restrict__ pe) {
    const int D4 = CD / 4;
    int i = blockIdx.x * 256 + threadIdx.x;
    float4 a = reinterpret_cast<const float4*>(x)[i];
    int row = i / D4;
    int pei = (row & (CS - 1)) * D4 + (i - row * D4);
    float4 p = reinterpret_cast<const float4*>(pe)[pei];
    a.x += p.x; a.y += p.y; a.z += p.z; a.w += p.w;
    reinterpret_cast<float4*>(g_h)[i] = a;
}

// ---------------- LayerNorm over last dim (1024), one block per row ---------
__global__ void __launch_bounds__(256) k_ln(const float* __restrict__ in,
                                            float* __restrict__ out,
                                            const float* __restrict__ gw,
                                            const float* __restrict__ bw) {
    __shared__ float s_s[8], s_q[8];
    const int row = blockIdx.x;
    const int t = threadIdx.x;
    float4 v = reinterpret_cast<const float4*>(in + (size_t)row * CD)[t];
    float s  = v.x + v.y + v.z + v.w;
    float q2 = v.x*v.x + v.y*v.y + v.z*v.z + v.w*v.w;
#pragma unroll
    for (int o = 16; o; o >>= 1) {
        s  += __shfl_xor_sync(0xffffffffu, s,  o);
        q2 += __shfl_xor_sync(0xffffffffu, q2, o);
    }
    if ((t & 31) == 0) { s_s[t >> 5] = s; s_q[t >> 5] = q2; }
    __syncthreads();
    if (t == 0) {
        float a = 0.f, b2 = 0.f;
#pragma unroll
        for (int w = 0; w < 8; w++) { a += s_s[w]; b2 += s_q[w]; }
        s_s[0] = a; s_q[0] = b2;
    }
    __syncthreads();
    const float mu  = s_s[0] * (1.0f / CD);
    const float var = s_q[0] * (1.0f / CD) - mu * mu;
    const float inv = rsqrtf(var + 1e-5f);
    float4 g4 = reinterpret_cast<const float4*>(gw)[t];
    float4 b4 = reinterpret_cast<const float4*>(bw)[t];
    float4 o4;
    o4.x = (v.x - mu) * inv * g4.x + b4.x;
    o4.y = (v.y - mu) * inv * g4.y + b4.y;
    o4.z = (v.z - mu) * inv * g4.z + b4.z;
    o4.w = (v.w - mu) * inv * g4.w + b4.w;
    reinterpret_cast<float4*>(out + (size_t)row * CD)[t] = o4;
}

// ---------------- Tensor-core GEMM: C[M,N] = A[M,K] * B[N,K]^T (+residual) --
// tf32 mma.sync m16n8k8. 128x128 block tile, kt=32, 8 warps (warp tile 32x64).
// Shared layout: m-major, stride 40 words, column = k ^ (m&4) swizzle.
#define GSTR 40
#define GBUF (128*GSTR)

__global__ void __launch_bounds__(256, 2) k_gemm_tc(const float* __restrict__ A,
                                                    const float* __restrict__ B,
                                                    const float* Res, float* C,
                                                    int N, int K, int addRes) {
    extern __shared__ uint32_t sh[];
    uint32_t* Abuf = sh;               // [2][128][GSTR]
    uint32_t* Bbuf = sh + 2*GBUF;      // [2][128][GSTR]

    const int tid  = threadIdx.x;
    const int lane = tid & 31;
    const int wid  = tid >> 5;
    const int g    = lane >> 2;        // group id 0..7
    const int tig  = lane & 3;         // thread-in-group 0..3
    const int m0   = (wid & 3) * 32;   // warp m offset in tile
    const int n0   = (wid >> 2) * 64;  // warp n offset in tile
    const int brow = blockIdx.y << 7;
    const int bcol = blockIdx.x << 7;

    const int srow = tid >> 3;         // staging row 0..31 (+32i)
    const int skq  = (tid & 7) << 2;   // staging k offset 0,4,...,28

    float acc[2][8][4] = {};

    const int nk = K >> 5;             // k-tiles of 32

    // stage tile kt into buffer buf
    auto stage = [&](int buf, int k0) {
        const float* Ag = A + (size_t)(brow + srow) * K + k0 + skq;
        const float* Bg = B + (size_t)(bcol + srow) * K + k0 + skq;
        uint32_t* Ad = Abuf + buf * GBUF;
        uint32_t* Bd = Bbuf + buf * GBUF;
#pragma unroll
        for (int i = 0; i < 4; i++) {
            int m = srow + i * 32;
            int col = skq ^ (m & 4);
            float4 va = *reinterpret_cast<const float4*>(Ag + (size_t)(i*32) * K);
            uint4 ua = make_uint4(f2tf(va.x), f2tf(va.y), f2tf(va.z), f2tf(va.w));
            *reinterpret_cast<uint4*>(&Ad[m * GSTR + col]) = ua;
            float4 vb = *reinterpret_cast<const float4*>(Bg + (size_t)(i*32) * K);
            uint4 ub = make_uint4(f2tf(vb.x), f2tf(vb.y), f2tf(vb.z), f2tf(vb.w));
            *reinterpret_cast<uint4*>(&Bd[m * GSTR + col]) = ub;
        }
    };

    stage(0, 0);
    __syncthreads();

    for (int kt = 0; kt < nk; kt++) {
        const int cur = kt & 1;
        if (kt + 1 < nk) stage(1 - cur, (kt + 1) << 5);

        const uint32_t* Ac = Abuf + cur * GBUF;
        const uint32_t* Bc = Bbuf + cur * GBUF;
#pragma unroll
        for (int kk = 0; kk < 32; kk += 8) {
            uint32_t af[2][4];
#pragma unroll
            for (int mt = 0; mt < 2; mt++) {
                int r  = m0 + mt*16 + g;
                int sw = r & 4;
                const uint32_t* R1 = Ac + r * GSTR;
                const uint32_t* R2 = Ac + (r + 8) * GSTR;
                af[mt][0] = R1[(kk + tig)     ^ sw];
                af[mt][1] = R2[(kk + tig)     ^ sw];
                af[mt][2] = R1[(kk + tig + 4) ^ sw];
                af[mt][3] = R2[(kk + tig + 4) ^ sw];
            }
#pragma unroll
            for (int nt = 0; nt < 8; nt++) {
                int n  = n0 + nt*8 + g;
                int sw = n & 4;
                uint32_t bf[2];
                bf[0] = Bc[n * GSTR + ((kk + tig)     ^ sw)];
                bf[1] = Bc[n * GSTR + ((kk + tig + 4) ^ sw)];
                mma_tf32(acc[0][nt], af[0], bf);
                mma_tf32(acc[1][nt], af[1], bf);
            }
        }
        __syncthreads();
    }

#pragma unroll
    for (int mt = 0; mt < 2; mt++) {
        int row = brow + m0 + mt*16 + g;
#pragma unroll
        for (int nt = 0; nt < 8; nt++) {
            int col = bcol + n0 + nt*8 + 2*tig;
            float2 v0 = make_float2(acc[mt][nt][0], acc[mt][nt][1]);
            float2 v1 = make_float2(acc[mt][nt][2], acc[mt][nt][3]);
            if (addRes) {
                float2 r0 = *reinterpret_cast<const float2*>(Res + (size_t)row * N + col);
                float2 r1 = *reinterpret_cast<const float2*>(Res + (size_t)(row+8) * N + col);
                v0.x += r0.x; v0.y += r0.y;
                v1.x += r1.x; v1.y += r1.y;
            }
            *reinterpret_cast<float2*>(C + (size_t)row * N + col)     = v0;
            *reinterpret_cast<float2*>(C + (size_t)(row+8) * N + col) = v1;
        }
    }
}

// ---------------- scores = (Q.K^T)*scale, TC, lower-triangular tiles --------
// Grid (kb, qb, bh). 64x64 tile, 128 threads (4 warps, warp = 16q x 64k slab).
#define ASTR 72
__global__ void __launch_bounds__(128) k_scores_tc() {
    const int kb = blockIdx.x, qb = blockIdx.y;
    if (kb > qb) return;
    const int bh = blockIdx.z;
    const int b = bh >> 4, h = bh & 15;

    __shared__ uint32_t Qs[64 * ASTR];
    __shared__ uint32_t Ks[64 * ASTR];

    const int tid  = threadIdx.x;
    const int lane = tid & 31;
    const int wid  = tid >> 5;
    const int g    = lane >> 2;
    const int tig  = lane & 3;

    // stage Q and K tiles (64 x 64), tf32, swizzled
    {
        const int r0 = tid >> 4;            // 0..7
        const int c4 = (tid & 15) << 2;     // 0,4,...,60
        const float* Qg = g_q + ((size_t)(b*CS + qb*64 + r0)) * CD + h*64 + c4;
        const float* Kg = g_k + ((size_t)(b*CS + kb*64 + r0)) * CD + h*64 + c4;
#pragma unroll
        for (int i = 0; i < 8; i++) {
            int m = r0 + i*8;
            int col = c4 ^ (m & 4);
            float4 vq = *reinterpret_cast<const float4*>(Qg + (size_t)(i*8) * CD);
            *reinterpret_cast<uint4*>(&Qs[m*ASTR + col]) =
                make_uint4(f2tf(vq.x), f2tf(vq.y), f2tf(vq.z), f2tf(vq.w));
            float4 vk = *reinterpret_cast<const float4*>(Kg + (size_t)(i*8) * CD);
            *reinterpret_cast<uint4*>(&Ks[m*ASTR + col]) =
                make_uint4(f2tf(vk.x), f2tf(vk.y), f2tf(vk.z), f2tf(vk.w));
        }
    }
    __syncthreads();

    float acc[8][4] = {};
    const int r = wid * 16 + g;
    const int swa = r & 4;
#pragma unroll
    for (int kk = 0; kk < 64; kk += 8) {
        uint32_t af[4];
        af[0] = Qs[r*ASTR       + ((kk + tig)     ^ swa)];
        af[1] = Qs[(r+8)*ASTR   + ((kk + tig)     ^ swa)];
        af[2] = Qs[r*ASTR       + ((kk + tig + 4) ^ swa)];
        af[3] = Qs[(r+8)*ASTR   + ((kk + tig + 4) ^ swa)];
#pragma unroll
        for (int nt = 0; nt < 8; nt++) {
            int n  = nt*8 + g;
            int sw = n & 4;
            uint32_t bf[2];
            bf[0] = Ks[n*ASTR + ((kk + tig)     ^ sw)];
            bf[1] = Ks[n*ASTR + ((kk + tig + 4) ^ sw)];
            mma_tf32(acc[nt], af, bf);
        }
    }

    const float scale = 0.125f;   // 1/sqrt(64)
    float* Sg = g_sc + ((size_t)bh * CS + qb*64 + wid*16 + g) * CS + kb*64;
#pragma unroll
    for (int nt = 0; nt < 8; nt++) {
        int col = nt*8 + 2*tig;
        *reinterpret_cast<float2*>(Sg + col) =
            make_float2(acc[nt][0]*scale, acc[nt][1]*scale);
        *reinterpret_cast<float2*>(Sg + (size_t)8 * CS + col) =
            make_float2(acc[nt][2]*scale, acc[nt][3]*scale);
    }
}

// ---------------- causal softmax over row q ----------------------------------
__global__ void __launch_bounds__(128) k_softmax() {
    __shared__ float smax[4], ssum[4];
    const size_t row = blockIdx.x;
    const int q = blockIdx.x & (CS - 1);
    float* p = g_sc + row * CS;
    const int n = q + 1;
    const int t = threadIdx.x;

    float m = -1e30f;
    for (int k = t; k < n; k += 128) m = fmaxf(m, p[k]);
#pragma unroll
    for (int o = 16; o; o >>= 1) m = fmaxf(m, __shfl_xor_sync(0xffffffffu, m, o));
    if ((t & 31) == 0) smax[t >> 5] = m;
    __syncthreads();
    m = fmaxf(fmaxf(smax[0], smax[1]), fmaxf(smax[2], smax[3]));

    float s = 0.f;
    for (int k = t; k < n; k += 128) { float e = __expf(p[k] - m); p[k] = e; s += e; }
#pragma unroll
    for (int o = 16; o; o >>= 1) s += __shfl_xor_sync(0xffffffffu, s, o);
    if ((t & 31) == 0) ssum[t >> 5] = s;
    __syncthreads();
    s = ssum[0] + ssum[1] + ssum[2] + ssum[3];
    const float inv = 1.0f / s;
    for (int k = t; k < n; k += 128) p[k] *= inv;

    const int kend = ((q >> 6) + 1) << 6;
    for (int k = n + t; k < kend; k += 128) p[k] = 0.f;
}

// ---------------- attn = P.V, TC, causal (kb <= qb) --------------------------
// Grid (qb, bh). Output 64q x 64hd, 128 threads, warp = 16q slab.
__global__ void __launch_bounds__(128) k_attnv_tc() {
    const int qb = blockIdx.x;
    const int bh = blockIdx.y;
    const int b = bh >> 4, h = bh & 15;

    __shared__ uint32_t Ps[64 * ASTR];   // [q][k], swizzled
    __shared__ uint32_t Vs[64 * ASTR];   // [k][n], no swizzle

    const int tid  = threadIdx.x;
    const int lane = tid & 31;
    const int wid  = tid >> 5;
    const int g    = lane >> 2;
    const int tig  = lane & 3;

    const int r0 = tid >> 4;
    const int c4 = (tid & 15) << 2;

    float acc[8][4] = {};
    const int rq  = wid * 16 + g;
    const int swa = rq & 4;

    const float* Pg0 = g_sc + ((size_t)bh * CS + qb*64 + r0) * CS + c4;
    const float* Vg0 = g_v + ((size_t)(b*CS + r0)) * CD + h*64 + c4;

    for (int kb = 0; kb <= qb; kb++) {
        // stage P (swizzled) and V
#pragma unroll
        for (int i = 0; i < 8; i++) {
            int m = r0 + i*8;
            int col = c4 ^ (m & 4);
            float4 vp = *reinterpret_cast<const float4*>(Pg0 + (size_t)(i*8) * CS + kb*64);
            *reinterpret_cast<uint4*>(&Ps[m*ASTR + col]) =
                make_uint4(f2tf(vp.x), f2tf(vp.y), f2tf(vp.z), f2tf(vp.w));
            float4 vv = *reinterpret_cast<const float4*>(Vg0 + (size_t)(kb*64 + i*8) * CD);
            *reinterpret_cast<uint4*>(&Vs[m*ASTR + c4]) =
                make_uint4(f2tf(vv.x), f2tf(vv.y), f2tf(vv.z), f2tf(vv.w));
        }
        __syncthreads();

#pragma unroll
        for (int kk = 0; kk < 64; kk += 8) {
            uint32_t af[4];
            af[0] = Ps[rq*ASTR     + ((kk + tig)     ^ swa)];
            af[1] = Ps[(rq+8)*ASTR + ((kk + tig)     ^ swa)];
            af[2] = Ps[rq*ASTR     + ((kk + tig + 4) ^ swa)];
            af[3] = Ps[(rq+8)*ASTR + ((kk + tig + 4) ^ swa)];
#pragma unroll
            for (int nt = 0; nt < 8; nt++) {
                int n = nt*8 + g;
                uint32_t bf[2];
                bf[0] = Vs[(kk + tig)     * ASTR + n];
                bf[1] = Vs[(kk + tig + 4) * ASTR + n];
                mma_tf32(acc[nt], af, bf);
            }
        }
        __syncthreads();
    }

    float* Og = g_at + ((size_t)(b*CS + qb*64 + wid*16 + g)) * CD + h*64;
#pragma unroll
    for (int nt = 0; nt < 8; nt++) {
        int col = nt*8 + 2*tig;
        *reinterpret_cast<float2*>(Og + col) = make_float2(acc[nt][0], acc[nt][1]);
        *reinterpret_cast<float2*>(Og + (size_t)8 * CD + col) = make_float2(acc[nt][2], acc[nt][3]);
    }
}

// ---------------- launch -----------------------------------------------------
extern "C" void kernel_launch(void* const* d_in, const int* in_sizes, int n_in,
                              void* d_out, int out_size) {
    const float* x    = (const float*)d_in[0];
    const float* pe   = (const float*)d_in[1];
    const float* ln1g = (const float*)d_in[3];
    const float* ln1b = (const float*)d_in[4];
    const float* wq   = (const float*)d_in[5];
    const float* wk   = (const float*)d_in[6];
    const float* wv   = (const float*)d_in[7];
    const float* wo   = (const float*)d_in[8];
    const float* ln2g = (const float*)d_in[9];
    const float* ln2b = (const float*)d_in[10];
    const float* wf   = (const float*)d_in[11];
    const float* lnfg = (const float*)d_in[12];
    const float* lnfb = (const float*)d_in[13];
    const float* wout = (const float*)d_in[14];

    float *ph, *phn, *pq, *pk, *pv, *pat;
    cudaGetSymbolAddress((void**)&ph,  g_h);
    cudaGetSymbolAddress((void**)&phn, g_hn);
    cudaGetSymbolAddress((void**)&pq,  g_q);
    cudaGetSymbolAddress((void**)&pk,  g_k);
    cudaGetSymbolAddress((void**)&pv,  g_v);
    cudaGetSymbolAddress((void**)&pat, g_at);

    const int gemmSmem = 4 * GBUF * (int)sizeof(uint32_t);   // 81920 B
    cudaFuncSetAttribute(k_gemm_tc, cudaFuncAttributeMaxDynamicSharedMemorySize, gemmSmem);

    k_addpe<<<(CM * CD / 4) / 256, 256>>>(x, pe);

    const dim3 gProj(CD / 128, CM / 128);    // (8, 32)
    const dim3 gOut (COUT / 128, CM / 128);  // (4, 32)
    const dim3 gSc  (CS / 64, CS / 64, CB * CH);
    const dim3 gAv  (CS / 64, CB * CH);

    for (int l = 0; l < CL; l++) {
        const size_t od  = (size_t)l * CD;
        const size_t odd = (size_t)l * CD * CD;
        k_ln<<<CM, 256>>>(ph, phn, ln1g + od, ln1b + od);
        k_gemm_tc<<<gProj, 256, gemmSmem>>>(phn, wq + odd, nullptr, pq, CD, CD, 0);
        k_gemm_tc<<<gProj, 256, gemmSmem>>>(phn, wk + odd, nullptr, pk, CD, CD, 0);
        k_gemm_tc<<<gProj, 256, gemmSmem>>>(phn, wv + odd, nullptr, pv, CD, CD, 0);
        k_scores_tc<<<gSc, 128>>>();
        k_softmax<<<CB * CH * CS, 128>>>();
        k_attnv_tc<<<gAv, 128>>>();
        k_gemm_tc<<<gProj, 256, gemmSmem>>>(pat, wo + odd, ph, ph, CD, CD, 1);
        k_ln<<<CM, 256>>>(ph, phn, ln2g + od, ln2b + od);
        k_gemm_tc<<<gProj, 256, gemmSmem>>>(phn, wf + odd, ph, ph, CD, CD, 1);
    }
    k_ln<<<CM, 256>>>(ph, phn, lnfg, lnfb);
    k_gemm_tc<<<gOut, 256, gemmSmem>>>(phn, wout, nullptr, (float*)d_out, COUT, CD, 0);
}

// round 5
// speedup vs baseline: 2.6616x; 1.1182x over previous
#include <cuda_runtime.h>
#include <math.h>
#include <stdint.h>

// Problem constants
#define CB   4
#define CS   1024
#define CD   1024
#define CH   16
#define CHD  64
#define CL   6
#define COUT 512
#define CM   (CB*CS)

// ---------------- scratch (device globals; no allocation allowed) ----------
__device__ float g_h [CM*CD];
__device__ float g_hn[CM*CD];
__device__ float g_q [CM*CD];
__device__ float g_k [CM*CD];
__device__ float g_v [CM*CD];
__device__ float g_at[CM*CD];
__device__ float g_sc[(size_t)CB*CH*CS*CS];          // 256 MB scores/probs
__device__ float g_wc[5*CL*CD*CD + COUT*CD];         // tf32-rounded weights

// ---------------- helpers ----------------------------------------------------
__device__ __forceinline__ uint32_t f2tf(float f) {
    uint32_t u;
    asm("cvt.rna.tf32.f32 %0, %1;" : "=r"(u) : "f"(f));
    return u;
}
__device__ __forceinline__ float rnd(float f) { return __uint_as_float(f2tf(f)); }

__device__ __forceinline__ void mma_tf32(float* c, const uint32_t* a, const uint32_t* b) {
    asm volatile(
        "mma.sync.aligned.m16n8k8.row.col.f32.tf32.tf32.f32 "
        "{%0,%1,%2,%3}, {%4,%5,%6,%7}, {%8,%9}, {%0,%1,%2,%3};\n"
        : "+f"(c[0]), "+f"(c[1]), "+f"(c[2]), "+f"(c[3])
        : "r"(a[0]), "r"(a[1]), "r"(a[2]), "r"(a[3]),
          "r"(b[0]), "r"(b[1]));
}

__device__ __forceinline__ void cpasync16(uint32_t dst, const void* src) {
    asm volatile("cp.async.ca.shared.global [%0], [%1], 16;\n" :: "r"(dst), "l"(src));
}
#define CP_COMMIT() asm volatile("cp.async.commit_group;\n" ::: "memory")
#define CP_WAIT(n)  asm volatile("cp.async.wait_group %0;\n" :: "n"(n) : "memory")

// ---------------- weight pre-round fp32 -> tf32 ------------------------------
__global__ void __launch_bounds__(256) k_cvtw(const float4* __restrict__ src,
                                              float4* __restrict__ dst) {
    int i = blockIdx.x * 256 + threadIdx.x;
    float4 v = src[i];
    v.x = rnd(v.x); v.y = rnd(v.y); v.z = rnd(v.z); v.w = rnd(v.w);
    dst[i] = v;
}

// ---------------- h = x + pe ------------------------------------------------
__global__ void __launch_bounds__(256) k_addpe(const float* __restrict__ x,
                                               const float* __restrict__ pe) {
    const int D4 = CD / 4;
    int i = blockIdx.x * 256 + threadIdx.x;
    float4 a = reinterpret_cast<const float4*>(x)[i];
    int row = i / D4;
    int pei = (row & (CS - 1)) * D4 + (i - row * D4);
    float4 p = reinterpret_cast<const float4*>(pe)[pei];
    a.x += p.x; a.y += p.y; a.z += p.z; a.w += p.w;
    reinterpret_cast<float4*>(g_h)[i] = a;
}

// ---------------- LayerNorm; output is tf32-rounded (only feeds GEMMs) ------
__global__ void __launch_bounds__(256) k_ln(const float* __restrict__ in,
                                            float* __restrict__ out,
                                            const float* __restrict__ gw,
                                            const float* __restrict__ bw) {
    __shared__ float s_s[8], s_q[8];
    const int row = blockIdx.x;
    const int t = threadIdx.x;
    float4 v = reinterpret_cast<const float4*>(in + (size_t)row * CD)[t];
    float s  = v.x + v.y + v.z + v.w;
    float q2 = v.x*v.x + v.y*v.y + v.z*v.z + v.w*v.w;
#pragma unroll
    for (int o = 16; o; o >>= 1) {
        s  += __shfl_xor_sync(0xffffffffu, s,  o);
        q2 += __shfl_xor_sync(0xffffffffu, q2, o);
    }
    if ((t & 31) == 0) { s_s[t >> 5] = s; s_q[t >> 5] = q2; }
    __syncthreads();
    if (t == 0) {
        float a = 0.f, b2 = 0.f;
#pragma unroll
        for (int w = 0; w < 8; w++) { a += s_s[w]; b2 += s_q[w]; }
        s_s[0] = a; s_q[0] = b2;
    }
    __syncthreads();
    const float mu  = s_s[0] * (1.0f / CD);
    const float var = s_q[0] * (1.0f / CD) - mu * mu;
    const float inv = rsqrtf(var + 1e-5f);
    float4 g4 = reinterpret_cast<const float4*>(gw)[t];
    float4 b4 = reinterpret_cast<const float4*>(bw)[t];
    float4 o4;
    o4.x = rnd((v.x - mu) * inv * g4.x + b4.x);
    o4.y = rnd((v.y - mu) * inv * g4.y + b4.y);
    o4.z = rnd((v.z - mu) * inv * g4.z + b4.z);
    o4.w = rnd((v.w - mu) * inv * g4.w + b4.w);
    reinterpret_cast<float4*>(out + (size_t)row * CD)[t] = o4;
}

// ---------------- Tensor-core GEMM: C[M,N] = A[M,K]*B[N,K]^T (+res, +round) -
// Inputs pre-rounded to tf32. cp.async double-buffered 128x128x32 pipeline.
#define GSTR 40
#define GBUF (128*GSTR)

__global__ void __launch_bounds__(256, 2) k_gemm_tc(const float* __restrict__ A,
                                                    const float* __restrict__ B,
                                                    const float* Res, float* C,
                                                    int N, int K, int addRes, int roundC) {
    extern __shared__ uint32_t sh[];
    const uint32_t shb = (uint32_t)__cvta_generic_to_shared(sh);

    const int tid  = threadIdx.x;
    const int lane = tid & 31;
    const int wid  = tid >> 5;
    const int g    = lane >> 2;
    const int tig  = lane & 3;
    const int m0   = (wid & 3) * 32;
    const int n0   = (wid >> 2) * 64;
    const int brow = blockIdx.y << 7;
    const int bcol = blockIdx.x << 7;

    const int srow = tid >> 3;
    const int skq  = (tid & 7) << 2;

    float acc[2][8][4] = {};
    const int nk = K >> 5;

    const float* Ag = A + (size_t)(brow + srow) * K + skq;
    const float* Bg = B + (size_t)(bcol + srow) * K + skq;

    auto stage = [&](int buf, int k0) {
        const uint32_t Ad = shb + (uint32_t)(buf * GBUF) * 4u;
        const uint32_t Bd = shb + (uint32_t)((2 + buf) * GBUF) * 4u;
#pragma unroll
        for (int i = 0; i < 4; i++) {
            const int m = srow + i * 32;
            const int col = skq ^ (m & 4);
            cpasync16(Ad + (uint32_t)(m * GSTR + col) * 4u, Ag + (size_t)(i*32) * K + k0);
            cpasync16(Bd + (uint32_t)(m * GSTR + col) * 4u, Bg + (size_t)(i*32) * K + k0);
        }
    };

    stage(0, 0);
    CP_COMMIT();

    for (int kt = 0; kt < nk; kt++) {
        const int cur = kt & 1;
        if (kt + 1 < nk) {
            stage(1 - cur, (kt + 1) << 5);
            CP_COMMIT();
            CP_WAIT(1);
        } else {
            CP_WAIT(0);
        }
        __syncthreads();

        const uint32_t* Ac = sh + cur * GBUF;
        const uint32_t* Bc = sh + (2 + cur) * GBUF;
#pragma unroll
        for (int kk = 0; kk < 32; kk += 8) {
            uint32_t af[2][4];
#pragma unroll
            for (int mt = 0; mt < 2; mt++) {
                const int r  = m0 + mt*16 + g;
                const int sw = r & 4;
                const uint32_t* R1 = Ac + r * GSTR;
                const uint32_t* R2 = Ac + (r + 8) * GSTR;
                af[mt][0] = R1[(kk + tig)     ^ sw];
                af[mt][1] = R2[(kk + tig)     ^ sw];
                af[mt][2] = R1[(kk + tig + 4) ^ sw];
                af[mt][3] = R2[(kk + tig + 4) ^ sw];
            }
#pragma unroll
            for (int nt = 0; nt < 8; nt++) {
                const int n  = n0 + nt*8 + g;
                const int sw = n & 4;
                uint32_t bf[2];
                bf[0] = Bc[n * GSTR + ((kk + tig)     ^ sw)];
                bf[1] = Bc[n * GSTR + ((kk + tig + 4) ^ sw)];
                mma_tf32(acc[0][nt], af[0], bf);
                mma_tf32(acc[1][nt], af[1], bf);
            }
        }
        __syncthreads();
    }

#pragma unroll
    for (int mt = 0; mt < 2; mt++) {
        const int row = brow + m0 + mt*16 + g;
#pragma unroll
        for (int nt = 0; nt < 8; nt++) {
            const int col = bcol + n0 + nt*8 + 2*tig;
            float2 v0 = make_float2(acc[mt][nt][0], acc[mt][nt][1]);
            float2 v1 = make_float2(acc[mt][nt][2], acc[mt][nt][3]);
            if (addRes) {
                float2 r0 = *reinterpret_cast<const float2*>(Res + (size_t)row * N + col);
                float2 r1 = *reinterpret_cast<const float2*>(Res + (size_t)(row+8) * N + col);
                v0.x += r0.x; v0.y += r0.y;
                v1.x += r1.x; v1.y += r1.y;
            }
            if (roundC) {
                v0.x = rnd(v0.x); v0.y = rnd(v0.y);
                v1.x = rnd(v1.x); v1.y = rnd(v1.y);
            }
            *reinterpret_cast<float2*>(C + (size_t)row * N + col)     = v0;
            *reinterpret_cast<float2*>(C + (size_t)(row+8) * N + col) = v1;
        }
    }
}

// ---------------- scores = (Q.K^T)*scale, causal tiles, inputs pre-rounded --
#define ASTR 72
__global__ void __launch_bounds__(128) k_scores_tc() {
    const int kb = blockIdx.x, qb = blockIdx.y;
    if (kb > qb) return;
    const int bh = blockIdx.z;
    const int b = bh >> 4, h = bh & 15;

    __shared__ uint32_t Qs[64 * ASTR];
    __shared__ uint32_t Ks[64 * ASTR];

    const int tid  = threadIdx.x;
    const int lane = tid & 31;
    const int wid  = tid >> 5;
    const int g    = lane >> 2;
    const int tig  = lane & 3;

    {
        const int r0 = tid >> 4;
        const int c4 = (tid & 15) << 2;
        const float* Qg = g_q + ((size_t)(b*CS + qb*64 + r0)) * CD + h*64 + c4;
        const float* Kg = g_k + ((size_t)(b*CS + kb*64 + r0)) * CD + h*64 + c4;
#pragma unroll
        for (int i = 0; i < 8; i++) {
            const int m = r0 + i*8;
            const int col = c4 ^ (m & 4);
            float4 vq = *reinterpret_cast<const float4*>(Qg + (size_t)(i*8) * CD);
            *reinterpret_cast<float4*>(&Qs[m*ASTR + col]) = vq;
            float4 vk = *reinterpret_cast<const float4*>(Kg + (size_t)(i*8) * CD);
            *reinterpret_cast<float4*>(&Ks[m*ASTR + col]) = vk;
        }
    }
    __syncthreads();

    float acc[8][4] = {};
    const int r = wid * 16 + g;
    const int swa = r & 4;
#pragma unroll
    for (int kk = 0; kk < 64; kk += 8) {
        uint32_t af[4];
        af[0] = Qs[r*ASTR     + ((kk + tig)     ^ swa)];
        af[1] = Qs[(r+8)*ASTR + ((kk + tig)     ^ swa)];
        af[2] = Qs[r*ASTR     + ((kk + tig + 4) ^ swa)];
        af[3] = Qs[(r+8)*ASTR + ((kk + tig + 4) ^ swa)];
#pragma unroll
        for (int nt = 0; nt < 8; nt++) {
            const int n  = nt*8 + g;
            const int sw = n & 4;
            uint32_t bf[2];
            bf[0] = Ks[n*ASTR + ((kk + tig)     ^ sw)];
            bf[1] = Ks[n*ASTR + ((kk + tig + 4) ^ sw)];
            mma_tf32(acc[nt], af, bf);
        }
    }

    const float scale = 0.125f;
    float* Sg = g_sc + ((size_t)bh * CS + qb*64 + wid*16 + g) * CS + kb*64;
#pragma unroll
    for (int nt = 0; nt < 8; nt++) {
        const int col = nt*8 + 2*tig;
        *reinterpret_cast<float2*>(Sg + col) =
            make_float2(acc[nt][0]*scale, acc[nt][1]*scale);
        *reinterpret_cast<float2*>(Sg + (size_t)8 * CS + col) =
            make_float2(acc[nt][2]*scale, acc[nt][3]*scale);
    }
}

// ---------------- causal softmax; probs written tf32-rounded -----------------
__global__ void __launch_bounds__(128) k_softmax() {
    __shared__ float smax[4], ssum[4];
    const size_t row = blockIdx.x;
    const int q = blockIdx.x & (CS - 1);
    float* p = g_sc + row * CS;
    const int n = q + 1;
    const int t = threadIdx.x;

    float m = -1e30f;
    for (int k = t; k < n; k += 128) m = fmaxf(m, p[k]);
#pragma unroll
    for (int o = 16; o; o >>= 1) m = fmaxf(m, __shfl_xor_sync(0xffffffffu, m, o));
    if ((t & 31) == 0) smax[t >> 5] = m;
    __syncthreads();
    m = fmaxf(fmaxf(smax[0], smax[1]), fmaxf(smax[2], smax[3]));

    float s = 0.f;
    for (int k = t; k < n; k += 128) { float e = __expf(p[k] - m); p[k] = e; s += e; }
#pragma unroll
    for (int o = 16; o; o >>= 1) s += __shfl_xor_sync(0xffffffffu, s, o);
    if ((t & 31) == 0) ssum[t >> 5] = s;
    __syncthreads();
    s = ssum[0] + ssum[1] + ssum[2] + ssum[3];
    const float inv = 1.0f / s;
    for (int k = t; k < n; k += 128) p[k] = rnd(p[k] * inv);

    const int kend = ((q >> 6) + 1) << 6;
    for (int k = n + t; k < kend; k += 128) p[k] = 0.f;
}

// ---------------- attn = P.V, causal; output tf32-rounded --------------------
__global__ void __launch_bounds__(128) k_attnv_tc() {
    const int qb = blockIdx.x;
    const int bh = blockIdx.y;
    const int b = bh >> 4, h = bh & 15;

    __shared__ uint32_t Ps[64 * ASTR];
    __shared__ uint32_t Vs[64 * ASTR];

    const int tid  = threadIdx.x;
    const int lane = tid & 31;
    const int wid  = tid >> 5;
    const int g    = lane >> 2;
    const int tig  = lane & 3;

    const int r0 = tid >> 4;
    const int c4 = (tid & 15) << 2;

    float acc[8][4] = {};
    const int rq  = wid * 16 + g;
    const int swa = rq & 4;

    const float* Pg0 = g_sc + ((size_t)bh * CS + qb*64 + r0) * CS + c4;
    const float* Vg0 = g_v + ((size_t)(b*CS + r0)) * CD + h*64 + c4;

    for (int kb = 0; kb <= qb; kb++) {
#pragma unroll
        for (int i = 0; i < 8; i++) {
            const int m = r0 + i*8;
            const int col = c4 ^ (m & 4);
            float4 vp = *reinterpret_cast<const float4*>(Pg0 + (size_t)(i*8) * CS + kb*64);
            *reinterpret_cast<float4*>(&Ps[m*ASTR + col]) = vp;
            float4 vv = *reinterpret_cast<const float4*>(Vg0 + (size_t)(kb*64 + i*8) * CD);
            *reinterpret_cast<float4*>(&Vs[m*ASTR + c4]) = vv;
        }
        __syncthreads();

#pragma unroll
        for (int kk = 0; kk < 64; kk += 8) {
            uint32_t af[4];
            af[0] = Ps[rq*ASTR     + ((kk + tig)     ^ swa)];
            af[1] = Ps[(rq+8)*ASTR + ((kk + tig)     ^ swa)];
            af[2] = Ps[rq*ASTR     + ((kk + tig + 4) ^ swa)];
            af[3] = Ps[(rq+8)*ASTR + ((kk + tig + 4) ^ swa)];
#pragma unroll
            for (int nt = 0; nt < 8; nt++) {
                const int n = nt*8 + g;
                uint32_t bf[2];
                bf[0] = Vs[(kk + tig)     * ASTR + n];
                bf[1] = Vs[(kk + tig + 4) * ASTR + n];
                mma_tf32(acc[nt], af, bf);
            }
        }
        __syncthreads();
    }

    float* Og = g_at + ((size_t)(b*CS + qb*64 + wid*16 + g)) * CD + h*64;
#pragma unroll
    for (int nt = 0; nt < 8; nt++) {
        const int col = nt*8 + 2*tig;
        *reinterpret_cast<float2*>(Og + col) =
            make_float2(rnd(acc[nt][0]), rnd(acc[nt][1]));
        *reinterpret_cast<float2*>(Og + (size_t)8 * CD + col) =
            make_float2(rnd(acc[nt][2]), rnd(acc[nt][3]));
    }
}

// ---------------- launch -----------------------------------------------------
extern "C" void kernel_launch(void* const* d_in, const int* in_sizes, int n_in,
                              void* d_out, int out_size) {
    const float* x    = (const float*)d_in[0];
    const float* pe   = (const float*)d_in[1];
    const float* ln1g = (const float*)d_in[3];
    const float* ln1b = (const float*)d_in[4];
    const float* wq   = (const float*)d_in[5];
    const float* wk   = (const float*)d_in[6];
    const float* wv   = (const float*)d_in[7];
    const float* wo   = (const float*)d_in[8];
    const float* ln2g = (const float*)d_in[9];
    const float* ln2b = (const float*)d_in[10];
    const float* wf   = (const float*)d_in[11];
    const float* lnfg = (const float*)d_in[12];
    const float* lnfb = (const float*)d_in[13];
    const float* wout = (const float*)d_in[14];

    float *ph, *phn, *pq, *pk, *pv, *pat, *pwc;
    cudaGetSymbolAddress((void**)&ph,  g_h);
    cudaGetSymbolAddress((void**)&phn, g_hn);
    cudaGetSymbolAddress((void**)&pq,  g_q);
    cudaGetSymbolAddress((void**)&pk,  g_k);
    cudaGetSymbolAddress((void**)&pv,  g_v);
    cudaGetSymbolAddress((void**)&pat, g_at);
    cudaGetSymbolAddress((void**)&pwc, g_wc);

    const size_t WSZ = (size_t)CL * CD * CD;          // 6M floats per weight family
    float* cwq = pwc + 0*WSZ;
    float* cwk = pwc + 1*WSZ;
    float* cwv = pwc + 2*WSZ;
    float* cwo = pwc + 3*WSZ;
    float* cwf = pwc + 4*WSZ;
    float* cwout = pwc + 5*WSZ;

    const int gemmSmem = 4 * GBUF * (int)sizeof(uint32_t);   // 81920 B
    cudaFuncSetAttribute(k_gemm_tc, cudaFuncAttributeMaxDynamicSharedMemorySize, gemmSmem);

    // weight pre-rounding (per call; deterministic)
    const int gW = (int)(WSZ / 4 / 256);              // 6144 blocks
    k_cvtw<<<gW, 256>>>((const float4*)wq, (float4*)cwq);
    k_cvtw<<<gW, 256>>>((const float4*)wk, (float4*)cwk);
    k_cvtw<<<gW, 256>>>((const float4*)wv, (float4*)cwv);
    k_cvtw<<<gW, 256>>>((const float4*)wo, (float4*)cwo);
    k_cvtw<<<gW, 256>>>((const float4*)wf, (float4*)cwf);
    k_cvtw<<<(COUT*CD/4)/256, 256>>>((const float4*)wout, (float4*)cwout);

    k_addpe<<<(CM * CD / 4) / 256, 256>>>(x, pe);

    const dim3 gProj(CD / 128, CM / 128);
    const dim3 gOut (COUT / 128, CM / 128);
    const dim3 gSc  (CS / 64, CS / 64, CB * CH);
    const dim3 gAv  (CS / 64, CB * CH);

    for (int l = 0; l < CL; l++) {
        const size_t od  = (size_t)l * CD;
        const size_t odd = (size_t)l * CD * CD;
        k_ln<<<CM, 256>>>(ph, phn, ln1g + od, ln1b + od);
        k_gemm_tc<<<gProj, 256, gemmSmem>>>(phn, cwq + odd, nullptr, pq, CD, CD, 0, 1);
        k_gemm_tc<<<gProj, 256, gemmSmem>>>(phn, cwk + odd, nullptr, pk, CD, CD, 0, 1);
        k_gemm_tc<<<gProj, 256, gemmSmem>>>(phn, cwv + odd, nullptr, pv, CD, CD, 0, 1);
        k_scores_tc<<<gSc, 128>>>();
        k_softmax<<<CB * CH * CS, 128>>>();
        k_attnv_tc<<<gAv, 128>>>();
        k_gemm_tc<<<gProj, 256, gemmSmem>>>(pat, cwo + odd, ph, ph, CD, CD, 1, 0);
        k_ln<<<CM, 256>>>(ph, phn, ln2g + od, ln2b + od);
        k_gemm_tc<<<gProj, 256, gemmSmem>>>(phn, cwf + odd, ph, ph, CD, CD, 1, 0);
    }
    k_ln<<<CM, 256>>>(ph, phn, lnfg, lnfb);
    k_gemm_tc<<<gOut, 256, gemmSmem>>>(phn, cwout, nullptr, (float*)d_out, COUT, CD, 0, 0);
}

// round 9
// speedup vs baseline: 3.1303x; 1.1761x over previous
#include <cuda_runtime.h>
#include <math.h>
#include <stdint.h>

// Problem constants
#define CB   4
#define CS   1024
#define CD   1024
#define CH   16
#define CHD  64
#define CL   6
#define COUT 512
#define CM   (CB*CS)

// ---------------- scratch (device globals; no allocation allowed) ----------
__device__ float g_h [CM*CD];
__device__ float g_hn[CM*CD];
__device__ float g_q [CM*CD];
__device__ float g_k [CM*CD];
__device__ float g_v [CM*CD];
__device__ float g_at[CM*CD];
__device__ float g_wc[5*CL*CD*CD + COUT*CD];         // tf32-rounded weights

// ---------------- helpers ----------------------------------------------------
__device__ __forceinline__ uint32_t f2tf(float f) {
    uint32_t u;
    asm("cvt.rna.tf32.f32 %0, %1;" : "=r"(u) : "f"(f));
    return u;
}
__device__ __forceinline__ float rnd(float f) { return __uint_as_float(f2tf(f)); }

__device__ __forceinline__ void mma_tf32(float* c, const uint32_t* a, const uint32_t* b) {
    asm volatile(
        "mma.sync.aligned.m16n8k8.row.col.f32.tf32.tf32.f32 "
        "{%0,%1,%2,%3}, {%4,%5,%6,%7}, {%8,%9}, {%0,%1,%2,%3};\n"
        : "+f"(c[0]), "+f"(c[1]), "+f"(c[2]), "+f"(c[3])
        : "r"(a[0]), "r"(a[1]), "r"(a[2]), "r"(a[3]),
          "r"(b[0]), "r"(b[1]));
}

__device__ __forceinline__ void cpasync16(uint32_t dst, const void* src) {
    asm volatile("cp.async.ca.shared.global [%0], [%1], 16;\n" :: "r"(dst), "l"(src));
}
#define CP_COMMIT() asm volatile("cp.async.commit_group;\n" ::: "memory")
#define CP_WAIT(n)  asm volatile("cp.async.wait_group %0;\n" :: "n"(n) : "memory")

// ---------------- weight pre-round fp32 -> tf32 ------------------------------
__global__ void __launch_bounds__(256) k_cvtw(const float4* __restrict__ src,
                                              float4* __restrict__ dst) {
    int i = blockIdx.x * 256 + threadIdx.x;
    float4 v = src[i];
    v.x = rnd(v.x); v.y = rnd(v.y); v.z = rnd(v.z); v.w = rnd(v.w);
    dst[i] = v;
}

// ---------------- h = x + pe ------------------------------------------------
__global__ void __launch_bounds__(256) k_addpe(const float* __restrict__ x,
                                               const float* __restrict__ pe) {
    const int D4 = CD / 4;
    int i = blockIdx.x * 256 + threadIdx.x;
    float4 a = reinterpret_cast<const float4*>(x)[i];
    int row = i / D4;
    int pei = (row & (CS - 1)) * D4 + (i - row * D4);
    float4 p = reinterpret_cast<const float4*>(pe)[pei];
    a.x += p.x; a.y += p.y; a.z += p.z; a.w += p.w;
    reinterpret_cast<float4*>(g_h)[i] = a;
}

// ---------------- LayerNorm; output tf32-rounded (only feeds GEMMs) ---------
__global__ void __launch_bounds__(256) k_ln(const float* __restrict__ in,
                                            float* __restrict__ out,
                                            const float* __restrict__ gw,
                                            const float* __restrict__ bw) {
    __shared__ float s_s[8], s_q[8];
    const int row = blockIdx.x;
    const int t = threadIdx.x;
    float4 v = reinterpret_cast<const float4*>(in + (size_t)row * CD)[t];
    float s  = v.x + v.y + v.z + v.w;
    float q2 = v.x*v.x + v.y*v.y + v.z*v.z + v.w*v.w;
#pragma unroll
    for (int o = 16; o; o >>= 1) {
        s  += __shfl_xor_sync(0xffffffffu, s,  o);
        q2 += __shfl_xor_sync(0xffffffffu, q2, o);
    }
    if ((t & 31) == 0) { s_s[t >> 5] = s; s_q[t >> 5] = q2; }
    __syncthreads();
    if (t == 0) {
        float a = 0.f, b2 = 0.f;
#pragma unroll
        for (int w = 0; w < 8; w++) { a += s_s[w]; b2 += s_q[w]; }
        s_s[0] = a; s_q[0] = b2;
    }
    __syncthreads();
    const float mu  = s_s[0] * (1.0f / CD);
    const float var = s_q[0] * (1.0f / CD) - mu * mu;
    const float inv = rsqrtf(var + 1e-5f);
    float4 g4 = reinterpret_cast<const float4*>(gw)[t];
    float4 b4 = reinterpret_cast<const float4*>(bw)[t];
    float4 o4;
    o4.x = rnd((v.x - mu) * inv * g4.x + b4.x);
    o4.y = rnd((v.y - mu) * inv * g4.y + b4.y);
    o4.z = rnd((v.z - mu) * inv * g4.z + b4.z);
    o4.w = rnd((v.w - mu) * inv * g4.w + b4.w);
    reinterpret_cast<float4*>(out + (size_t)row * CD)[t] = o4;
}

// ---------------- Tensor-core GEMM: C[M,N] = A[M,K]*B[N,K]^T (+res, +round) -
#define GSTR 40
#define GBUF (128*GSTR)

__global__ void __launch_bounds__(256, 2) k_gemm_tc(const float* __restrict__ A,
                                                    const float* __restrict__ B,
                                                    const float* Res, float* C,
                                                    int N, int K, int addRes, int roundC) {
    extern __shared__ uint32_t sh[];
    const uint32_t shb = (uint32_t)__cvta_generic_to_shared(sh);

    const int tid  = threadIdx.x;
    const int lane = tid & 31;
    const int wid  = tid >> 5;
    const int g    = lane >> 2;
    const int tig  = lane & 3;
    const int m0   = (wid & 3) * 32;
    const int n0   = (wid >> 2) * 64;
    const int brow = blockIdx.y << 7;
    const int bcol = blockIdx.x << 7;

    const int srow = tid >> 3;
    const int skq  = (tid & 7) << 2;

    float acc[2][8][4] = {};
    const int nk = K >> 5;

    const float* Ag = A + (size_t)(brow + srow) * K + skq;
    const float* Bg = B + (size_t)(bcol + srow) * K + skq;

    auto stage = [&](int buf, int k0) {
        const uint32_t Ad = shb + (uint32_t)(buf * GBUF) * 4u;
        const uint32_t Bd = shb + (uint32_t)((2 + buf) * GBUF) * 4u;
#pragma unroll
        for (int i = 0; i < 4; i++) {
            const int m = srow + i * 32;
            const int col = skq ^ (m & 4);
            cpasync16(Ad + (uint32_t)(m * GSTR + col) * 4u, Ag + (size_t)(i*32) * K + k0);
            cpasync16(Bd + (uint32_t)(m * GSTR + col) * 4u, Bg + (size_t)(i*32) * K + k0);
        }
    };

    stage(0, 0);
    CP_COMMIT();

    for (int kt = 0; kt < nk; kt++) {
        const int cur = kt & 1;
        if (kt + 1 < nk) {
            stage(1 - cur, (kt + 1) << 5);
            CP_COMMIT();
            CP_WAIT(1);
        } else {
            CP_WAIT(0);
        }
        __syncthreads();

        const uint32_t* Ac = sh + cur * GBUF;
        const uint32_t* Bc = sh + (2 + cur) * GBUF;
#pragma unroll
        for (int kk = 0; kk < 32; kk += 8) {
            uint32_t af[2][4];
#pragma unroll
            for (int mt = 0; mt < 2; mt++) {
                const int r  = m0 + mt*16 + g;
                const int sw = r & 4;
                const uint32_t* R1 = Ac + r * GSTR;
                const uint32_t* R2 = Ac + (r + 8) * GSTR;
                af[mt][0] = R1[(kk + tig)     ^ sw];
                af[mt][1] = R2[(kk + tig)     ^ sw];
                af[mt][2] = R1[(kk + tig + 4) ^ sw];
                af[mt][3] = R2[(kk + tig + 4) ^ sw];
            }
#pragma unroll
            for (int nt = 0; nt < 8; nt++) {
                const int n  = n0 + nt*8 + g;
                const int sw = n & 4;
                uint32_t bf[2];
                bf[0] = Bc[n * GSTR + ((kk + tig)     ^ sw)];
                bf[1] = Bc[n * GSTR + ((kk + tig + 4) ^ sw)];
                mma_tf32(acc[0][nt], af[0], bf);
                mma_tf32(acc[1][nt], af[1], bf);
            }
        }
        __syncthreads();
    }

#pragma unroll
    for (int mt = 0; mt < 2; mt++) {
        const int row = brow + m0 + mt*16 + g;
#pragma unroll
        for (int nt = 0; nt < 8; nt++) {
            const int col = bcol + n0 + nt*8 + 2*tig;
            float2 v0 = make_float2(acc[mt][nt][0], acc[mt][nt][1]);
            float2 v1 = make_float2(acc[mt][nt][2], acc[mt][nt][3]);
            if (addRes) {
                float2 r0 = *reinterpret_cast<const float2*>(Res + (size_t)row * N + col);
                float2 r1 = *reinterpret_cast<const float2*>(Res + (size_t)(row+8) * N + col);
                v0.x += r0.x; v0.y += r0.y;
                v1.x += r1.x; v1.y += r1.y;
            }
            if (roundC) {
                v0.x = rnd(v0.x); v0.y = rnd(v0.y);
                v1.x = rnd(v1.x); v1.y = rnd(v1.y);
            }
            *reinterpret_cast<float2*>(C + (size_t)row * N + col)     = v0;
            *reinterpret_cast<float2*>(C + (size_t)(row+8) * N + col) = v1;
        }
    }
}

// ---------------- fused flash attention --------------------------------------
// One block = 64 q-rows x one (b,h). 128 threads / 4 warps; warp = 16 q-rows.
// Q held in registers; K/V cp.async double-buffered; online softmax; P via
// warp-private smem round-trip; O accumulated in registers.
#define FSTR 72
#define FT   (64*FSTR)
// smem: K[2] | V[2] | P   -> 5 * FT words = 92160 B
__global__ void __launch_bounds__(128) k_flash() {
    extern __shared__ uint32_t fsh[];
    const uint32_t shb = (uint32_t)__cvta_generic_to_shared(fsh);
    uint32_t* Ps = fsh + 4*FT;

    const int qb = 15 - blockIdx.x;            // heavy tiles first
    const int bh = blockIdx.y;
    const int b  = bh >> 4, h = bh & 15;

    const int tid  = threadIdx.x;
    const int lane = tid & 31;
    const int wid  = tid >> 5;
    const int g    = lane >> 2;
    const int tig  = lane & 3;

    const int r0 = tid >> 4;                   // 0..7  (staging row)
    const int c4 = (tid & 15) << 2;            // 0..60 (staging col)

    const int rq  = wid*16 + g;                // this thread's tile row (and +8)
    const int swa = rq & 4;

    // ---- load Q tile into registers (stage through Ps) ----
    uint32_t qf[8][4];
    {
        const float* Qg = g_q + ((size_t)(b*CS + qb*64 + r0)) * CD + h*64 + c4;
#pragma unroll
        for (int i = 0; i < 8; i++) {
            const int m = r0 + i*8;
            *reinterpret_cast<float4*>(&Ps[m*FSTR + (c4 ^ (m & 4))]) =
                *reinterpret_cast<const float4*>(Qg + (size_t)(i*8) * CD);
        }
        __syncthreads();
#pragma unroll
        for (int k8 = 0; k8 < 8; k8++) {
            const int kk = k8*8;
            qf[k8][0] = Ps[rq*FSTR     + ((kk + tig)     ^ swa)];
            qf[k8][1] = Ps[(rq+8)*FSTR + ((kk + tig)     ^ swa)];
            qf[k8][2] = Ps[rq*FSTR     + ((kk + tig + 4) ^ swa)];
            qf[k8][3] = Ps[(rq+8)*FSTR + ((kk + tig + 4) ^ swa)];
        }
        __syncthreads();
    }

    float accO[8][4] = {};
    float mrow[2] = {-1e30f, -1e30f};
    float lrow[2] = {0.f, 0.f};

    const float* Kg = g_k + ((size_t)(b*CS + r0)) * CD + h*64 + c4;
    const float* Vg = g_v + ((size_t)(b*CS + r0)) * CD + h*64 + c4;

    auto stageKV = [&](int buf, int kb) {
        const uint32_t Kd = shb + (uint32_t)(buf * FT) * 4u;
        const uint32_t Vd = shb + (uint32_t)((2 + buf) * FT) * 4u;
#pragma unroll
        for (int i = 0; i < 8; i++) {
            const int m = r0 + i*8;
            cpasync16(Kd + (uint32_t)(m*FSTR + (c4 ^ (m & 4))) * 4u,
                      Kg + (size_t)(kb*64 + i*8) * CD);
            cpasync16(Vd + (uint32_t)(m*FSTR + c4) * 4u,
                      Vg + (size_t)(kb*64 + i*8) * CD);
        }
    };

    stageKV(0, 0);
    CP_COMMIT();

    for (int kb = 0; kb <= qb; kb++) {
        const int cur = kb & 1;
        if (kb < qb) {
            stageKV(1 - cur, kb + 1);
            CP_COMMIT();
            CP_WAIT(1);
        } else {
            CP_WAIT(0);
        }
        __syncthreads();

        const uint32_t* Ks = fsh + cur * FT;
        const uint32_t* Vs = fsh + (2 + cur) * FT;

        // ---- S = Q.K^T ----
        float accS[8][4] = {};
#pragma unroll
        for (int k8 = 0; k8 < 8; k8++) {
            const int kk = k8*8;
#pragma unroll
            for (int nt = 0; nt < 8; nt++) {
                const int n  = nt*8 + g;
                const int sw = n & 4;
                uint32_t bf[2];
                bf[0] = Ks[n*FSTR + ((kk + tig)     ^ sw)];
                bf[1] = Ks[n*FSTR + ((kk + tig + 4) ^ sw)];
                mma_tf32(accS[nt], qf[k8], bf);
            }
        }

        // ---- scale + causal mask ----
        const float scale = 0.125f;
#pragma unroll
        for (int nt = 0; nt < 8; nt++) {
#pragma unroll
            for (int e = 0; e < 4; e++) accS[nt][e] *= scale;
            if (kb == qb) {
                const int col = nt*8 + 2*tig;
                if (col     > rq)   accS[nt][0] = -1e30f;
                if (col + 1 > rq)   accS[nt][1] = -1e30f;
                if (col     > rq+8) accS[nt][2] = -1e30f;
                if (col + 1 > rq+8) accS[nt][3] = -1e30f;
            }
        }

        // ---- online softmax: new row max (quad reduction) ----
        float mn0 = mrow[0], mn1 = mrow[1];
#pragma unroll
        for (int nt = 0; nt < 8; nt++) {
            mn0 = fmaxf(mn0, fmaxf(accS[nt][0], accS[nt][1]));
            mn1 = fmaxf(mn1, fmaxf(accS[nt][2], accS[nt][3]));
        }
#pragma unroll
        for (int o = 1; o <= 2; o <<= 1) {
            mn0 = fmaxf(mn0, __shfl_xor_sync(0xffffffffu, mn0, o));
            mn1 = fmaxf(mn1, __shfl_xor_sync(0xffffffffu, mn1, o));
        }
        const float fac0 = __expf(mrow[0] - mn0);
        const float fac1 = __expf(mrow[1] - mn1);
        mrow[0] = mn0; mrow[1] = mn1;
        lrow[0] *= fac0; lrow[1] *= fac1;

        // ---- P = exp(S - m) (tf32-rounded), accumulate l, rescale O, store P
        float ps0 = 0.f, ps1 = 0.f;
#pragma unroll
        for (int nt = 0; nt < 8; nt++) {
            uint32_t p0 = f2tf(__expf(accS[nt][0] - mn0));
            uint32_t p1 = f2tf(__expf(accS[nt][1] - mn0));
            uint32_t p2 = f2tf(__expf(accS[nt][2] - mn1));
            uint32_t p3 = f2tf(__expf(accS[nt][3] - mn1));
            ps0 += __uint_as_float(p0) + __uint_as_float(p1);
            ps1 += __uint_as_float(p2) + __uint_as_float(p3);
            const int col = (2*tig) ^ swa;
            *reinterpret_cast<uint2*>(&Ps[rq*FSTR     + nt*8 + col]) = make_uint2(p0, p1);
            *reinterpret_cast<uint2*>(&Ps[(rq+8)*FSTR + nt*8 + col]) = make_uint2(p2, p3);
            accO[nt][0] *= fac0; accO[nt][1] *= fac0;
            accO[nt][2] *= fac1; accO[nt][3] *= fac1;
        }
        // row-sum contribution (quad reduce; every lane keeps the total)
#pragma unroll
        for (int o = 1; o <= 2; o <<= 1) {
            ps0 += __shfl_xor_sync(0xffffffffu, ps0, o);
            ps1 += __shfl_xor_sync(0xffffffffu, ps1, o);
        }
        lrow[0] += ps0; lrow[1] += ps1;
        __syncwarp();

        // ---- O += P.V ----
#pragma unroll
        for (int k8 = 0; k8 < 8; k8++) {
            const int kk = k8*8;
            uint32_t af[4];
            af[0] = Ps[rq*FSTR     + ((kk + tig)     ^ swa)];
            af[1] = Ps[(rq+8)*FSTR + ((kk + tig)     ^ swa)];
            af[2] = Ps[rq*FSTR     + ((kk + tig + 4) ^ swa)];
            af[3] = Ps[(rq+8)*FSTR + ((kk + tig + 4) ^ swa)];
#pragma unroll
            for (int nt = 0; nt < 8; nt++) {
                const int n = nt*8 + g;
                uint32_t bf[2];
                bf[0] = Vs[(kk + tig)     * FSTR + n];
                bf[1] = Vs[(kk + tig + 4) * FSTR + n];
                mma_tf32(accO[nt], af, bf);
            }
        }
        __syncthreads();
    }

    // ---- normalize and store (tf32-rounded; feeds Wo GEMM) ----
    const float inv0 = 1.0f / lrow[0];
    const float inv1 = 1.0f / lrow[1];
    float* Og = g_at + ((size_t)(b*CS + qb*64 + rq)) * CD + h*64;
#pragma unroll
    for (int nt = 0; nt < 8; nt++) {
        const int col = nt*8 + 2*tig;
        *reinterpret_cast<float2*>(Og + col) =
            make_float2(rnd(accO[nt][0]*inv0), rnd(accO[nt][1]*inv0));
        *reinterpret_cast<float2*>(Og + (size_t)8 * CD + col) =
            make_float2(rnd(accO[nt][2]*inv1), rnd(accO[nt][3]*inv1));
    }
}

// ---------------- launch -----------------------------------------------------
extern "C" void kernel_launch(void* const* d_in, const int* in_sizes, int n_in,
                              void* d_out, int out_size) {
    const float* x    = (const float*)d_in[0];
    const float* pe   = (const float*)d_in[1];
    const float* ln1g = (const float*)d_in[3];
    const float* ln1b = (const float*)d_in[4];
    const float* wq   = (const float*)d_in[5];
    const float* wk   = (const float*)d_in[6];
    const float* wv   = (const float*)d_in[7];
    const float* wo   = (const float*)d_in[8];
    const float* ln2g = (const float*)d_in[9];
    const float* ln2b = (const float*)d_in[10];
    const float* wf   = (const float*)d_in[11];
    const float* lnfg = (const float*)d_in[12];
    const float* lnfb = (const float*)d_in[13];
    const float* wout = (const float*)d_in[14];

    float *ph, *phn, *pq, *pk, *pv, *pat, *pwc;
    cudaGetSymbolAddress((void**)&ph,  g_h);
    cudaGetSymbolAddress((void**)&phn, g_hn);
    cudaGetSymbolAddress((void**)&pq,  g_q);
    cudaGetSymbolAddress((void**)&pk,  g_k);
    cudaGetSymbolAddress((void**)&pv,  g_v);
    cudaGetSymbolAddress((void**)&pat, g_at);
    cudaGetSymbolAddress((void**)&pwc, g_wc);

    const size_t WSZ = (size_t)CL * CD * CD;
    float* cwq = pwc + 0*WSZ;
    float* cwk = pwc + 1*WSZ;
    float* cwv = pwc + 2*WSZ;
    float* cwo = pwc + 3*WSZ;
    float* cwf = pwc + 4*WSZ;
    float* cwout = pwc + 5*WSZ;

    const int gemmSmem  = 4 * GBUF * (int)sizeof(uint32_t);   // 81920 B
    const int flashSmem = 5 * FT   * (int)sizeof(uint32_t);   // 92160 B
    cudaFuncSetAttribute(k_gemm_tc, cudaFuncAttributeMaxDynamicSharedMemorySize, gemmSmem);
    cudaFuncSetAttribute(k_flash,   cudaFuncAttributeMaxDynamicSharedMemorySize, flashSmem);

    const int gW = (int)(WSZ / 4 / 256);
    k_cvtw<<<gW, 256>>>((const float4*)wq, (float4*)cwq);
    k_cvtw<<<gW, 256>>>((const float4*)wk, (float4*)cwk);
    k_cvtw<<<gW, 256>>>((const float4*)wv, (float4*)cwv);
    k_cvtw<<<gW, 256>>>((const float4*)wo, (float4*)cwo);
    k_cvtw<<<gW, 256>>>((const float4*)wf, (float4*)cwf);
    k_cvtw<<<(COUT*CD/4)/256, 256>>>((const float4*)wout, (float4*)cwout);

    k_addpe<<<(CM * CD / 4) / 256, 256>>>(x, pe);

    const dim3 gProj(CD / 128, CM / 128);
    const dim3 gOut (COUT / 128, CM / 128);
    const dim3 gFl  (CS / 64, CB * CH);

    for (int l = 0; l < CL; l++) {
        const size_t od  = (size_t)l * CD;
        const size_t odd = (size_t)l * CD * CD;
        k_ln<<<CM, 256>>>(ph, phn, ln1g + od, ln1b + od);
        k_gemm_tc<<<gProj, 256, gemmSmem>>>(phn, cwq + odd, nullptr, pq, CD, CD, 0, 1);
        k_gemm_tc<<<gProj, 256, gemmSmem>>>(phn, cwk + odd, nullptr, pk, CD, CD, 0, 1);
        k_gemm_tc<<<gProj, 256, gemmSmem>>>(phn, cwv + odd, nullptr, pv, CD, CD, 0, 1);
        k_flash<<<gFl, 128, flashSmem>>>();
        k_gemm_tc<<<gProj, 256, gemmSmem>>>(pat, cwo + odd, ph, ph, CD, CD, 1, 0);
        k_ln<<<CM, 256>>>(ph, phn, ln2g + od, ln2b + od);
        k_gemm_tc<<<gProj, 256, gemmSmem>>>(phn, cwf + odd, ph, ph, CD, CD, 1, 0);
    }
    k_ln<<<CM, 256>>>(ph, phn, lnfg, lnfb);
    k_gemm_tc<<<gOut, 256, gemmSmem>>>(phn, cwout, nullptr, (float*)d_out, COUT, CD, 0, 0);
}

// round 14
// speedup vs baseline: 3.1868x; 1.0181x over previous
#include <cuda_runtime.h>
#include <math.h>
#include <stdint.h>

// Problem constants
#define CB   4
#define CS   1024
#define CD   1024
#define CH   16
#define CHD  64
#define CL   6
#define COUT 512
#define CM   (CB*CS)
#define QKVS (3*CD)          // fused qkv row stride

// ---------------- scratch (device globals; no allocation allowed) ----------
__device__ float g_h  [CM*CD];
__device__ float g_hn [CM*CD];          // LN out, permuted-k (GEMM A operand)
__device__ float g_qkv[CM*QKVS];        // fused q|k|v, natural layout
__device__ float g_at [CM*CD];          // flash out, permuted-k (GEMM A operand)
__device__ float g_wc [5*CL*CD*CD + COUT*CD];   // tf32-rounded, permuted-k weights

// ---------------- helpers ----------------------------------------------------
__device__ __forceinline__ uint32_t f2tf(float f) {
    uint32_t u;
    asm("cvt.rna.tf32.f32 %0, %1;" : "=r"(u) : "f"(f));
    return u;
}
__device__ __forceinline__ float rnd(float f) { return __uint_as_float(f2tf(f)); }

__device__ __forceinline__ void mma_tf32(float* c, const uint32_t* a, const uint32_t* b) {
    asm volatile(
        "mma.sync.aligned.m16n8k8.row.col.f32.tf32.tf32.f32 "
        "{%0,%1,%2,%3}, {%4,%5,%6,%7}, {%8,%9}, {%0,%1,%2,%3};\n"
        : "+f"(c[0]), "+f"(c[1]), "+f"(c[2]), "+f"(c[3])
        : "r"(a[0]), "r"(a[1]), "r"(a[2]), "r"(a[3]),
          "r"(b[0]), "r"(b[1]));
}

__device__ __forceinline__ void cpasync16(uint32_t dst, const void* src) {
    asm volatile("cp.async.ca.shared.global [%0], [%1], 16;\n" :: "r"(dst), "l"(src));
}
#define CP_COMMIT() asm volatile("cp.async.commit_group;\n" ::: "memory")
#define CP_WAIT(n)  asm volatile("cp.async.wait_group %0;\n" :: "n"(n) : "memory")

// ---------------- weight pre-round + k-permute (fp32 -> tf32) ---------------
// Within each 32-wide k block, element k = 4q + r is stored at p = r*8 + q.
__global__ void __launch_bounds__(256) k_cvtw(const float* __restrict__ src,
                                              float* __restrict__ dst) {
    int i = blockIdx.x * 256 + threadIdx.x;          // float4 index
    float4 v = reinterpret_cast<const float4*>(src)[i];
    const size_t e0 = (size_t)i * 4;
    float* op = dst + (e0 & ~(size_t)31) + ((e0 >> 2) & 7);
    op[0]  = rnd(v.x);
    op[8]  = rnd(v.y);
    op[16] = rnd(v.z);
    op[24] = rnd(v.w);
}

// fused QKV weight convert: family f = blockIdx.y (0=q,1=k,2=v); per-layer
// interleave dst layer l occupies rows [l*3072, (l+1)*3072), family f rows
// [f*1024, f*1024+1024) within the layer.
__global__ void __launch_bounds__(256) k_cvtw3(const float* __restrict__ wq,
                                               const float* __restrict__ wk,
                                               const float* __restrict__ wv,
                                               float* __restrict__ dst) {
    int i = blockIdx.x * 256 + threadIdx.x;          // float4 index over CL*CD*CD/4
    const float* src = blockIdx.y == 0 ? wq : (blockIdx.y == 1 ? wk : wv);
    float4 v = reinterpret_cast<const float4*>(src)[i];
    const size_t e0 = (size_t)i * 4;
    const size_t l  = e0 >> 20;                      // CD*CD = 1M = 2^20
    const size_t w  = e0 & ((1u << 20) - 1);
    float* op = dst + l * (3u << 20) + ((size_t)blockIdx.y << 20)
                    + (w & ~(size_t)31) + ((w >> 2) & 7);
    op[0]  = rnd(v.x);
    op[8]  = rnd(v.y);
    op[16] = rnd(v.z);
    op[24] = rnd(v.w);
}

// ---------------- h = x + pe ------------------------------------------------
__global__ void __launch_bounds__(256) k_addpe(const float* __restrict__ x,
                                               const float* __restrict__ pe) {
    const int D4 = CD / 4;
    int i = blockIdx.x * 256 + threadIdx.x;
    float4 a = reinterpret_cast<const float4*>(x)[i];
    int row = i / D4;
    int pei = (row & (CS - 1)) * D4 + (i - row * D4);
    float4 p = reinterpret_cast<const float4*>(pe)[pei];
    a.x += p.x; a.y += p.y; a.z += p.z; a.w += p.w;
    reinterpret_cast<float4*>(g_h)[i] = a;
}

// ---------------- LayerNorm; tf32-rounded, permuted-k output ----------------
__global__ void __launch_bounds__(256) k_ln(const float* __restrict__ in,
                                            float* __restrict__ out,
                                            const float* __restrict__ gw,
                                            const float* __restrict__ bw) {
    __shared__ float s_s[8], s_q[8];
    const int row = blockIdx.x;
    const int t = threadIdx.x;
    float4 v = reinterpret_cast<const float4*>(in + (size_t)row * CD)[t];
    float s  = v.x + v.y + v.z + v.w;
    float q2 = v.x*v.x + v.y*v.y + v.z*v.z + v.w*v.w;
#pragma unroll
    for (int o = 16; o; o >>= 1) {
        s  += __shfl_xor_sync(0xffffffffu, s,  o);
        q2 += __shfl_xor_sync(0xffffffffu, q2, o);
    }
    if ((t & 31) == 0) { s_s[t >> 5] = s; s_q[t >> 5] = q2; }
    __syncthreads();
    if (t == 0) {
        float a = 0.f, b2 = 0.f;
#pragma unroll
        for (int w = 0; w < 8; w++) { a += s_s[w]; b2 += s_q[w]; }
        s_s[0] = a; s_q[0] = b2;
    }
    __syncthreads();
    const float mu  = s_s[0] * (1.0f / CD);
    const float var = s_q[0] * (1.0f / CD) - mu * mu;
    const float inv = rsqrtf(var + 1e-5f);
    float4 g4 = reinterpret_cast<const float4*>(gw)[t];
    float4 b4 = reinterpret_cast<const float4*>(bw)[t];
    // permuted store: cols 4t..4t+3 -> block base + q, +8, +16, +24
    float* op = out + (size_t)row * CD + ((t << 2) & ~31) + (t & 7);
    op[0]  = rnd((v.x - mu) * inv * g4.x + b4.x);
    op[8]  = rnd((v.y - mu) * inv * g4.y + b4.y);
    op[16] = rnd((v.z - mu) * inv * g4.z + b4.z);
    op[24] = rnd((v.w - mu) * inv * g4.w + b4.w);
}

// ---------------- Tensor-core GEMM: C[M,N] = A[M,K]*B[N,K]^T (+res,+round) --
// A and B are permuted-k (p = r*8+q within 32-blocks) -> fragment loads are
// LDS.128. 128x128 block tile, kt=32, cp.async double buffer, 8 warps.
#define NSTR 36
#define NBUF (128*NSTR)

__global__ void __launch_bounds__(256, 2) k_gemm_tc(const float* __restrict__ A,
                                                    const float* __restrict__ B,
                                                    const float* Res, float* C,
                                                    int N, int K, int addRes, int roundC) {
    extern __shared__ uint32_t sh[];
    const uint32_t shb = (uint32_t)__cvta_generic_to_shared(sh);

    const int tid  = threadIdx.x;
    const int lane = tid & 31;
    const int wid  = tid >> 5;
    const int g    = lane >> 2;
    const int tig  = lane & 3;
    const int m0   = (wid & 3) * 32;
    const int n0   = (wid >> 2) * 64;
    const int brow = blockIdx.y << 7;
    const int bcol = blockIdx.x << 7;

    const int rowb = tid >> 3;            // 0..31
    const int ch   = tid & 7;             // 16B chunk

    float acc[2][8][4] = {};
    const int nk = K >> 5;

    const float* Ag = A + (size_t)(brow + rowb) * K + ch*4;
    const float* Bg = B + (size_t)(bcol + rowb) * K + ch*4;

    auto stage = [&](int buf, int k0) {
        const uint32_t Ad = shb + (uint32_t)(buf * NBUF) * 4u;
        const uint32_t Bd = shb + (uint32_t)((2 + buf) * NBUF) * 4u;
#pragma unroll
        for (int i = 0; i < 4; i++) {
            const int r = rowb + i*32;
            cpasync16(Ad + (uint32_t)(r * NSTR + ch*4) * 4u, Ag + (size_t)(i*32) * K + k0);
            cpasync16(Bd + (uint32_t)(r * NSTR + ch*4) * 4u, Bg + (size_t)(i*32) * K + k0);
        }
    };

    stage(0, 0);
    CP_COMMIT();

    for (int kt = 0; kt < nk; kt++) {
        const int cur = kt & 1;
        if (kt + 1 < nk) {
            stage(1 - cur, (kt + 1) << 5);
            CP_COMMIT();
            CP_WAIT(1);
        } else {
            CP_WAIT(0);
        }
        __syncthreads();

        const uint32_t* Ac = sh + cur * NBUF;
        const uint32_t* Bc = sh + (2 + cur) * NBUF;
#pragma unroll
        for (int kh = 0; kh < 2; kh++) {
            uint4 aU[2][2];
#pragma unroll
            for (int mt = 0; mt < 2; mt++)
#pragma unroll
                for (int rr = 0; rr < 2; rr++) {
                    const int row = m0 + mt*16 + rr*8 + g;
                    aU[mt][rr] = *reinterpret_cast<const uint4*>(&Ac[row*NSTR + tig*8 + kh*4]);
                }
            uint4 bU[8];
#pragma unroll
            for (int nt = 0; nt < 8; nt++) {
                const int n = n0 + nt*8 + g;
                bU[nt] = *reinterpret_cast<const uint4*>(&Bc[n*NSTR + tig*8 + kh*4]);
            }
            uint32_t af0[2][4] = {{aU[0][0].x, aU[0][1].x, aU[0][0].y, aU[0][1].y},
                                  {aU[1][0].x, aU[1][1].x, aU[1][0].y, aU[1][1].y}};
            uint32_t af1[2][4] = {{aU[0][0].z, aU[0][1].z, aU[0][0].w, aU[0][1].w},
                                  {aU[1][0].z, aU[1][1].z, aU[1][0].w, aU[1][1].w}};
#pragma unroll
            for (int nt = 0; nt < 8; nt++) {
                uint32_t bf0[2] = {bU[nt].x, bU[nt].y};
                mma_tf32(acc[0][nt], af0[0], bf0);
                mma_tf32(acc[1][nt], af0[1], bf0);
                uint32_t bf1[2] = {bU[nt].z, bU[nt].w};
                mma_tf32(acc[0][nt], af1[0], bf1);
                mma_tf32(acc[1][nt], af1[1], bf1);
            }
        }
        __syncthreads();
    }

#pragma unroll
    for (int mt = 0; mt < 2; mt++) {
        const int row = brow + m0 + mt*16 + g;
#pragma unroll
        for (int nt = 0; nt < 8; nt++) {
            const int col = bcol + n0 + nt*8 + 2*tig;
            float2 v0 = make_float2(acc[mt][nt][0], acc[mt][nt][1]);
            float2 v1 = make_float2(acc[mt][nt][2], acc[mt][nt][3]);
            if (addRes) {
                float2 r0 = *reinterpret_cast<const float2*>(Res + (size_t)row * N + col);
                float2 r1 = *reinterpret_cast<const float2*>(Res + (size_t)(row+8) * N + col);
                v0.x += r0.x; v0.y += r0.y;
                v1.x += r1.x; v1.y += r1.y;
            }
            if (roundC) {
                v0.x = rnd(v0.x); v0.y = rnd(v0.y);
                v1.x = rnd(v1.x); v1.y = rnd(v1.y);
            }
            *reinterpret_cast<float2*>(C + (size_t)row * N + col)     = v0;
            *reinterpret_cast<float2*>(C + (size_t)(row+8) * N + col) = v1;
        }
    }
}

// ---------------- fused flash attention --------------------------------------
// Reads Q/K/V from fused g_qkv (natural layout); writes O permuted-k to g_at.
#define FSTR 72
#define FT   (64*FSTR)
__global__ void __launch_bounds__(128) k_flash() {
    extern __shared__ uint32_t fsh[];
    const uint32_t shb = (uint32_t)__cvta_generic_to_shared(fsh);
    uint32_t* Ps = fsh + 4*FT;

    const int qb = 15 - blockIdx.x;
    const int bh = blockIdx.y;
    const int b  = bh >> 4, h = bh & 15;

    const int tid  = threadIdx.x;
    const int lane = tid & 31;
    const int wid  = tid >> 5;
    const int g    = lane >> 2;
    const int tig  = lane & 3;

    const int r0 = tid >> 4;
    const int c4 = (tid & 15) << 2;

    const int rq  = wid*16 + g;
    const int swa = rq & 4;

    uint32_t qf[8][4];
    {
        const float* Qg = g_qkv + ((size_t)(b*CS + qb*64 + r0)) * QKVS + h*64 + c4;
#pragma unroll
        for (int i = 0; i < 8; i++) {
            const int m = r0 + i*8;
            *reinterpret_cast<float4*>(&Ps[m*FSTR + (c4 ^ (m & 4))]) =
                *reinterpret_cast<const float4*>(Qg + (size_t)(i*8) * QKVS);
        }
        __syncthreads();
#pragma unroll
        for (int k8 = 0; k8 < 8; k8++) {
            const int kk = k8*8;
            qf[k8][0] = Ps[rq*FSTR     + ((kk + tig)     ^ swa)];
            qf[k8][1] = Ps[(rq+8)*FSTR + ((kk + tig)     ^ swa)];
            qf[k8][2] = Ps[rq*FSTR     + ((kk + tig + 4) ^ swa)];
            qf[k8][3] = Ps[(rq+8)*FSTR + ((kk + tig + 4) ^ swa)];
        }
        __syncthreads();
    }

    float accO[8][4] = {};
    float mrow[2] = {-1e30f, -1e30f};
    float lrow[2] = {0.f, 0.f};

    const float* Kg = g_qkv + ((size_t)(b*CS + r0)) * QKVS + CD   + h*64 + c4;
    const float* Vg = g_qkv + ((size_t)(b*CS + r0)) * QKVS + 2*CD + h*64 + c4;

    auto stageKV = [&](int buf, int kb) {
        const uint32_t Kd = shb + (uint32_t)(buf * FT) * 4u;
        const uint32_t Vd = shb + (uint32_t)((2 + buf) * FT) * 4u;
#pragma unroll
        for (int i = 0; i < 8; i++) {
            const int m = r0 + i*8;
            cpasync16(Kd + (uint32_t)(m*FSTR + (c4 ^ (m & 4))) * 4u,
                      Kg + (size_t)(kb*64 + i*8) * QKVS);
            cpasync16(Vd + (uint32_t)(m*FSTR + c4) * 4u,
                      Vg + (size_t)(kb*64 + i*8) * QKVS);
        }
    };

    stageKV(0, 0);
    CP_COMMIT();

    for (int kb = 0; kb <= qb; kb++) {
        const int cur = kb & 1;
        if (kb < qb) {
            stageKV(1 - cur, kb + 1);
            CP_COMMIT();
            CP_WAIT(1);
        } else {
            CP_WAIT(0);
        }
        __syncthreads();

        const uint32_t* Ks = fsh + cur * FT;
        const uint32_t* Vs = fsh + (2 + cur) * FT;

        float accS[8][4] = {};
#pragma unroll
        for (int k8 = 0; k8 < 8; k8++) {
            const int kk = k8*8;
#pragma unroll
            for (int nt = 0; nt < 8; nt++) {
                const int n  = nt*8 + g;
                const int sw = n & 4;
                uint32_t bf[2];
                bf[0] = Ks[n*FSTR + ((kk + tig)     ^ sw)];
                bf[1] = Ks[n*FSTR + ((kk + tig + 4) ^ sw)];
                mma_tf32(accS[nt], qf[k8], bf);
            }
        }

        const float scale = 0.125f;
#pragma unroll
        for (int nt = 0; nt < 8; nt++) {
#pragma unroll
            for (int e = 0; e < 4; e++) accS[nt][e] *= scale;
            if (kb == qb) {
                const int col = nt*8 + 2*tig;
                if (col     > rq)   accS[nt][0] = -1e30f;
                if (col + 1 > rq)   accS[nt][1] = -1e30f;
                if (col     > rq+8) accS[nt][2] = -1e30f;
                if (col + 1 > rq+8) accS[nt][3] = -1e30f;
            }
        }

        float mn0 = mrow[0], mn1 = mrow[1];
#pragma unroll
        for (int nt = 0; nt < 8; nt++) {
            mn0 = fmaxf(mn0, fmaxf(accS[nt][0], accS[nt][1]));
            mn1 = fmaxf(mn1, fmaxf(accS[nt][2], accS[nt][3]));
        }
#pragma unroll
        for (int o = 1; o <= 2; o <<= 1) {
            mn0 = fmaxf(mn0, __shfl_xor_sync(0xffffffffu, mn0, o));
            mn1 = fmaxf(mn1, __shfl_xor_sync(0xffffffffu, mn1, o));
        }
        const float fac0 = __expf(mrow[0] - mn0);
        const float fac1 = __expf(mrow[1] - mn1);
        mrow[0] = mn0; mrow[1] = mn1;
        lrow[0] *= fac0; lrow[1] *= fac1;

        float ps0 = 0.f, ps1 = 0.f;
#pragma unroll
        for (int nt = 0; nt < 8; nt++) {
            uint32_t p0 = f2tf(__expf(accS[nt][0] - mn0));
            uint32_t p1 = f2tf(__expf(accS[nt][1] - mn0));
            uint32_t p2 = f2tf(__expf(accS[nt][2] - mn1));
            uint32_t p3 = f2tf(__expf(accS[nt][3] - mn1));
            ps0 += __uint_as_float(p0) + __uint_as_float(p1);
            ps1 += __uint_as_float(p2) + __uint_as_float(p3);
            const int col = (2*tig) ^ swa;
            *reinterpret_cast<uint2*>(&Ps[rq*FSTR     + nt*8 + col]) = make_uint2(p0, p1);
            *reinterpret_cast<uint2*>(&Ps[(rq+8)*FSTR + nt*8 + col]) = make_uint2(p2, p3);
            accO[nt][0] *= fac0; accO[nt][1] *= fac0;
            accO[nt][2] *= fac1; accO[nt][3] *= fac1;
        }
#pragma unroll
        for (int o = 1; o <= 2; o <<= 1) {
            ps0 += __shfl_xor_sync(0xffffffffu, ps0, o);
            ps1 += __shfl_xor_sync(0xffffffffu, ps1, o);
        }
        lrow[0] += ps0; lrow[1] += ps1;
        __syncwarp();

#pragma unroll
        for (int k8 = 0; k8 < 8; k8++) {
            const int kk = k8*8;
            uint32_t af[4];
            af[0] = Ps[rq*FSTR     + ((kk + tig)     ^ swa)];
            af[1] = Ps[(rq+8)*FSTR + ((kk + tig)     ^ swa)];
            af[2] = Ps[rq*FSTR     + ((kk + tig + 4) ^ swa)];
            af[3] = Ps[(rq+8)*FSTR + ((kk + tig + 4) ^ swa)];
#pragma unroll
            for (int nt = 0; nt < 8; nt++) {
                const int n = nt*8 + g;
                uint32_t bf[2];
                bf[0] = Vs[(kk + tig)     * FSTR + n];
                bf[1] = Vs[(kk + tig + 4) * FSTR + n];
                mma_tf32(accO[nt], af, bf);
            }
        }
        __syncthreads();
    }

    // ---- normalize; store tf32-rounded, PERMUTED-K (feeds Wo GEMM as A) ----
    const float inv0 = 1.0f / lrow[0];
    const float inv1 = 1.0f / lrow[1];
    float* Og = g_at + ((size_t)(b*CS + qb*64 + rq)) * CD + h*64;
#pragma unroll
    for (int nt = 0; nt < 8; nt++) {
        const int c0 = nt*8 + 2*tig;
        const int c1 = c0 + 1;
        const int p0 = (c0 & ~31) | ((c0 & 3)*8 + ((c0 >> 2) & 7));
        const int p1 = (c1 & ~31) | ((c1 & 3)*8 + ((c1 >> 2) & 7));
        Og[p0] = rnd(accO[nt][0]*inv0);
        Og[p1] = rnd(accO[nt][1]*inv0);
        Og[(size_t)8*CD + p0] = rnd(accO[nt][2]*inv1);
        Og[(size_t)8*CD + p1] = rnd(accO[nt][3]*inv1);
    }
}

// ---------------- launch -----------------------------------------------------
extern "C" void kernel_launch(void* const* d_in, const int* in_sizes, int n_in,
                              void* d_out, int out_size) {
    const float* x    = (const float*)d_in[0];
    const float* pe   = (const float*)d_in[1];
    const float* ln1g = (const float*)d_in[3];
    const float* ln1b = (const float*)d_in[4];
    const float* wq   = (const float*)d_in[5];
    const float* wk   = (const float*)d_in[6];
    const float* wv   = (const float*)d_in[7];
    const float* wo   = (const float*)d_in[8];
    const float* ln2g = (const float*)d_in[9];
    const float* ln2b = (const float*)d_in[10];
    const float* wf   = (const float*)d_in[11];
    const float* lnfg = (const float*)d_in[12];
    const float* lnfb = (const float*)d_in[13];
    const float* wout = (const float*)d_in[14];

    float *ph, *phn, *pqkv, *pat, *pwc;
    cudaGetSymbolAddress((void**)&ph,   g_h);
    cudaGetSymbolAddress((void**)&phn,  g_hn);
    cudaGetSymbolAddress((void**)&pqkv, g_qkv);
    cudaGetSymbolAddress((void**)&pat,  g_at);
    cudaGetSymbolAddress((void**)&pwc,  g_wc);

    const size_t WSZ = (size_t)CL * CD * CD;         // 6M floats per family
    float* cwqkv = pwc;                              // [CL][3072][1024] interleaved
    float* cwo   = pwc + 3*WSZ;
    float* cwf   = pwc + 4*WSZ;
    float* cwout = pwc + 5*WSZ;

    const int gemmSmem  = 4 * NBUF * (int)sizeof(uint32_t);   // 73728 B
    const int flashSmem = 5 * FT   * (int)sizeof(uint32_t);   // 92160 B
    cudaFuncSetAttribute(k_gemm_tc, cudaFuncAttributeMaxDynamicSharedMemorySize, gemmSmem);
    cudaFuncSetAttribute(k_flash,   cudaFuncAttributeMaxDynamicSharedMemorySize, flashSmem);

    const int gW = (int)(WSZ / 4 / 256);             // 6144 blocks
    k_cvtw3<<<dim3(gW, 3), 256>>>(wq, wk, wv, cwqkv);
    k_cvtw<<<gW, 256>>>(wo, cwo);
    k_cvtw<<<gW, 256>>>(wf, cwf);
    k_cvtw<<<(COUT*CD/4)/256, 256>>>(wout, cwout);

    k_addpe<<<(CM * CD / 4) / 256, 256>>>(x, pe);

    const dim3 gQKV(QKVS / 128, CM / 128);   // (24, 32)
    const dim3 gProj(CD / 128, CM / 128);    // (8, 32)
    const dim3 gOut (COUT / 128, CM / 128);  // (4, 32)
    const dim3 gFl  (CS / 64, CB * CH);

    for (int l = 0; l < CL; l++) {
        const size_t od   = (size_t)l * CD;
        const size_t odd  = (size_t)l * CD * CD;
        const size_t odd3 = (size_t)l * 3 * CD * CD;
        k_ln<<<CM, 256>>>(ph, phn, ln1g + od, ln1b + od);
        k_gemm_tc<<<gQKV, 256, gemmSmem>>>(phn, cwqkv + odd3, nullptr, pqkv, QKVS, CD, 0, 1);
        k_flash<<<gFl, 128, flashSmem>>>();
        k_gemm_tc<<<gProj, 256, gemmSmem>>>(pat, cwo + odd, ph, ph, CD, CD, 1, 0);
        k_ln<<<CM, 256>>>(ph, phn, ln2g + od, ln2b + od);
        k_gemm_tc<<<gProj, 256, gemmSmem>>>(phn, cwf + odd, ph, ph, CD, CD, 1, 0);
    }
    k_ln<<<CM, 256>>>(ph, phn, lnfg, lnfb);
    k_gemm_tc<<<gOut, 256, gemmSmem>>>(phn, cwout, nullptr, (float*)d_out, COUT, CD, 0, 0);
}

// round 15
// speedup vs baseline: 3.2715x; 1.0266x over previous
#include <cuda_runtime.h>
#include <math.h>
#include <stdint.h>

// Problem constants
#define CB   4
#define CS   1024
#define CD   1024
#define CH   16
#define CHD  64
#define CL   6
#define COUT 512
#define CM   (CB*CS)
#define QKVS (3*CD)          // fused qkv row stride

// ---------------- scratch (device globals; no allocation allowed) ----------
__device__ float g_h  [CM*CD];
__device__ float g_hn [CM*CD];          // LN out, permuted-k (GEMM A operand)
__device__ float g_qkv[CM*QKVS];        // fused q|k|v, natural layout
__device__ float g_at [CM*CD];          // flash out, permuted-k (GEMM A operand)
__device__ float g_wc [5*CL*CD*CD + COUT*CD];   // tf32-rounded, permuted-k weights

// ---------------- helpers ----------------------------------------------------
__device__ __forceinline__ uint32_t f2tf(float f) {
    uint32_t u;
    asm("cvt.rna.tf32.f32 %0, %1;" : "=r"(u) : "f"(f));
    return u;
}
__device__ __forceinline__ float rnd(float f) { return __uint_as_float(f2tf(f)); }

__device__ __forceinline__ void mma_tf32(float* c, const uint32_t* a, const uint32_t* b) {
    asm volatile(
        "mma.sync.aligned.m16n8k8.row.col.f32.tf32.tf32.f32 "
        "{%0,%1,%2,%3}, {%4,%5,%6,%7}, {%8,%9}, {%0,%1,%2,%3};\n"
        : "+f"(c[0]), "+f"(c[1]), "+f"(c[2]), "+f"(c[3])
        : "r"(a[0]), "r"(a[1]), "r"(a[2]), "r"(a[3]),
          "r"(b[0]), "r"(b[1]));
}

__device__ __forceinline__ void cpasync16(uint32_t dst, const void* src) {
    asm volatile("cp.async.ca.shared.global [%0], [%1], 16;\n" :: "r"(dst), "l"(src));
}
#define CP_COMMIT() asm volatile("cp.async.commit_group;\n" ::: "memory")
#define CP_WAIT(n)  asm volatile("cp.async.wait_group %0;\n" :: "n"(n) : "memory")

// ---------------- weight pre-round + k-permute (fp32 -> tf32) ---------------
// Within each 32-wide k block, element k = 4q + r is stored at p = r*8 + q.
__global__ void __launch_bounds__(256) k_cvtw(const float* __restrict__ src,
                                              float* __restrict__ dst) {
    int i = blockIdx.x * 256 + threadIdx.x;          // float4 index
    float4 v = reinterpret_cast<const float4*>(src)[i];
    const size_t e0 = (size_t)i * 4;
    float* op = dst + (e0 & ~(size_t)31) + ((e0 >> 2) & 7);
    op[0]  = rnd(v.x);
    op[8]  = rnd(v.y);
    op[16] = rnd(v.z);
    op[24] = rnd(v.w);
}

// fused QKV weight convert: family f = blockIdx.y (0=q,1=k,2=v)
__global__ void __launch_bounds__(256) k_cvtw3(const float* __restrict__ wq,
                                               const float* __restrict__ wk,
                                               const float* __restrict__ wv,
                                               float* __restrict__ dst) {
    int i = blockIdx.x * 256 + threadIdx.x;          // float4 index over CL*CD*CD/4
    const float* src = blockIdx.y == 0 ? wq : (blockIdx.y == 1 ? wk : wv);
    float4 v = reinterpret_cast<const float4*>(src)[i];
    const size_t e0 = (size_t)i * 4;
    const size_t l  = e0 >> 20;
    const size_t w  = e0 & ((1u << 20) - 1);
    float* op = dst + l * (3u << 20) + ((size_t)blockIdx.y << 20)
                    + (w & ~(size_t)31) + ((w >> 2) & 7);
    op[0]  = rnd(v.x);
    op[8]  = rnd(v.y);
    op[16] = rnd(v.z);
    op[24] = rnd(v.w);
}

// ---------------- h = x + pe ------------------------------------------------
__global__ void __launch_bounds__(256) k_addpe(const float* __restrict__ x,
                                               const float* __restrict__ pe) {
    const int D4 = CD / 4;
    int i = blockIdx.x * 256 + threadIdx.x;
    float4 a = reinterpret_cast<const float4*>(x)[i];
    int row = i / D4;
    int pei = (row & (CS - 1)) * D4 + (i - row * D4);
    float4 p = reinterpret_cast<const float4*>(pe)[pei];
    a.x += p.x; a.y += p.y; a.z += p.z; a.w += p.w;
    reinterpret_cast<float4*>(g_h)[i] = a;
}

// ---------------- LayerNorm; tf32-rounded, permuted-k output ----------------
__global__ void __launch_bounds__(256) k_ln(const float* __restrict__ in,
                                            float* __restrict__ out,
                                            const float* __restrict__ gw,
                                            const float* __restrict__ bw) {
    __shared__ float s_s[8], s_q[8];
    const int row = blockIdx.x;
    const int t = threadIdx.x;
    float4 v = reinterpret_cast<const float4*>(in + (size_t)row * CD)[t];
    float s  = v.x + v.y + v.z + v.w;
    float q2 = v.x*v.x + v.y*v.y + v.z*v.z + v.w*v.w;
#pragma unroll
    for (int o = 16; o; o >>= 1) {
        s  += __shfl_xor_sync(0xffffffffu, s,  o);
        q2 += __shfl_xor_sync(0xffffffffu, q2, o);
    }
    if ((t & 31) == 0) { s_s[t >> 5] = s; s_q[t >> 5] = q2; }
    __syncthreads();
    if (t == 0) {
        float a = 0.f, b2 = 0.f;
#pragma unroll
        for (int w = 0; w < 8; w++) { a += s_s[w]; b2 += s_q[w]; }
        s_s[0] = a; s_q[0] = b2;
    }
    __syncthreads();
    const float mu  = s_s[0] * (1.0f / CD);
    const float var = s_q[0] * (1.0f / CD) - mu * mu;
    const float inv = rsqrtf(var + 1e-5f);
    float4 g4 = reinterpret_cast<const float4*>(gw)[t];
    float4 b4 = reinterpret_cast<const float4*>(bw)[t];
    float* op = out + (size_t)row * CD + ((t << 2) & ~31) + (t & 7);
    op[0]  = rnd((v.x - mu) * inv * g4.x + b4.x);
    op[8]  = rnd((v.y - mu) * inv * g4.y + b4.y);
    op[16] = rnd((v.z - mu) * inv * g4.z + b4.z);
    op[24] = rnd((v.w - mu) * inv * g4.w + b4.w);
}

// ---------------- Tensor-core GEMM: C[M,N] = A[M,K]*B[N,K]^T (+res,+round) --
// Permuted-k operands -> LDS.128 fragment loads. 128x128x32 tiles, cp.async
// double buffer, ONE barrier per k-tile, staging overlapped with compute.
#define NSTR 36
#define NBUF (128*NSTR)

__global__ void __launch_bounds__(256, 2) k_gemm_tc(const float* __restrict__ A,
                                                    const float* __restrict__ B,
                                                    const float* Res, float* C,
                                                    int N, int K, int addRes, int roundC) {
    extern __shared__ uint32_t sh[];
    const uint32_t shb = (uint32_t)__cvta_generic_to_shared(sh);

    const int tid  = threadIdx.x;
    const int lane = tid & 31;
    const int wid  = tid >> 5;
    const int g    = lane >> 2;
    const int tig  = lane & 3;
    const int m0   = (wid & 3) * 32;
    const int n0   = (wid >> 2) * 64;
    const int brow = blockIdx.y << 7;
    const int bcol = blockIdx.x << 7;

    const int rowb = tid >> 3;
    const int ch   = tid & 7;

    float acc[2][8][4] = {};
    const int nk = K >> 5;

    const float* Ag = A + (size_t)(brow + rowb) * K + ch*4;
    const float* Bg = B + (size_t)(bcol + rowb) * K + ch*4;

    auto stage = [&](int buf, int k0) {
        const uint32_t Ad = shb + (uint32_t)(buf * NBUF) * 4u;
        const uint32_t Bd = shb + (uint32_t)((2 + buf) * NBUF) * 4u;
#pragma unroll
        for (int i = 0; i < 4; i++) {
            const int r = rowb + i*32;
            cpasync16(Ad + (uint32_t)(r * NSTR + ch*4) * 4u, Ag + (size_t)(i*32) * K + k0);
            cpasync16(Bd + (uint32_t)(r * NSTR + ch*4) * 4u, Bg + (size_t)(i*32) * K + k0);
        }
    };

    stage(0, 0);
    CP_COMMIT();

    for (int kt = 0; kt < nk; kt++) {
        const int cur = kt & 1;
        CP_WAIT(0);
        __syncthreads();
        // stage NEXT tile into the buffer consumed at iter kt-1 (safe post-sync),
        // fully overlapped with this tile's MMA work.
        if (kt + 1 < nk) {
            stage(1 - cur, (kt + 1) << 5);
            CP_COMMIT();
        }

        const uint32_t* Ac = sh + cur * NBUF;
        const uint32_t* Bc = sh + (2 + cur) * NBUF;
#pragma unroll
        for (int kh = 0; kh < 2; kh++) {
            uint4 aU[2][2];
#pragma unroll
            for (int mt = 0; mt < 2; mt++)
#pragma unroll
                for (int rr = 0; rr < 2; rr++) {
                    const int row = m0 + mt*16 + rr*8 + g;
                    aU[mt][rr] = *reinterpret_cast<const uint4*>(&Ac[row*NSTR + tig*8 + kh*4]);
                }
            uint4 bU[8];
#pragma unroll
            for (int nt = 0; nt < 8; nt++) {
                const int n = n0 + nt*8 + g;
                bU[nt] = *reinterpret_cast<const uint4*>(&Bc[n*NSTR + tig*8 + kh*4]);
            }
            uint32_t af0[2][4] = {{aU[0][0].x, aU[0][1].x, aU[0][0].y, aU[0][1].y},
                                  {aU[1][0].x, aU[1][1].x, aU[1][0].y, aU[1][1].y}};
            uint32_t af1[2][4] = {{aU[0][0].z, aU[0][1].z, aU[0][0].w, aU[0][1].w},
                                  {aU[1][0].z, aU[1][1].z, aU[1][0].w, aU[1][1].w}};
#pragma unroll
            for (int nt = 0; nt < 8; nt++) {
                uint32_t bf0[2] = {bU[nt].x, bU[nt].y};
                mma_tf32(acc[0][nt], af0[0], bf0);
                mma_tf32(acc[1][nt], af0[1], bf0);
                uint32_t bf1[2] = {bU[nt].z, bU[nt].w};
                mma_tf32(acc[0][nt], af1[0], bf1);
                mma_tf32(acc[1][nt], af1[1], bf1);
            }
        }
        // no trailing barrier: next iteration's CP_WAIT+sync provides it
    }

#pragma unroll
    for (int mt = 0; mt < 2; mt++) {
        const int row = brow + m0 + mt*16 + g;
#pragma unroll
        for (int nt = 0; nt < 8; nt++) {
            const int col = bcol + n0 + nt*8 + 2*tig;
            float2 v0 = make_float2(acc[mt][nt][0], acc[mt][nt][1]);
            float2 v1 = make_float2(acc[mt][nt][2], acc[mt][nt][3]);
            if (addRes) {
                float2 r0 = *reinterpret_cast<const float2*>(Res + (size_t)row * N + col);
                float2 r1 = *reinterpret_cast<const float2*>(Res + (size_t)(row+8) * N + col);
                v0.x += r0.x; v0.y += r0.y;
                v1.x += r1.x; v1.y += r1.y;
            }
            if (roundC) {
                v0.x = rnd(v0.x); v0.y = rnd(v0.y);
                v1.x = rnd(v1.x); v1.y = rnd(v1.y);
            }
            *reinterpret_cast<float2*>(C + (size_t)row * N + col)     = v0;
            *reinterpret_cast<float2*>(C + (size_t)(row+8) * N + col) = v1;
        }
    }
}

// ---------------- fused flash attention --------------------------------------
// Same single-barrier pipeline restructure as the GEMM.
#define FSTR 72
#define FT   (64*FSTR)
__global__ void __launch_bounds__(128) k_flash() {
    extern __shared__ uint32_t fsh[];
    const uint32_t shb = (uint32_t)__cvta_generic_to_shared(fsh);
    uint32_t* Ps = fsh + 4*FT;

    const int qb = 15 - blockIdx.x;
    const int bh = blockIdx.y;
    const int b  = bh >> 4, h = bh & 15;

    const int tid  = threadIdx.x;
    const int lane = tid & 31;
    const int wid  = tid >> 5;
    const int g    = lane >> 2;
    const int tig  = lane & 3;

    const int r0 = tid >> 4;
    const int c4 = (tid & 15) << 2;

    const int rq  = wid*16 + g;
    const int swa = rq & 4;

    const float* Kg = g_qkv + ((size_t)(b*CS + r0)) * QKVS + CD   + h*64 + c4;
    const float* Vg = g_qkv + ((size_t)(b*CS + r0)) * QKVS + 2*CD + h*64 + c4;

    auto stageKV = [&](int buf, int kb) {
        const uint32_t Kd = shb + (uint32_t)(buf * FT) * 4u;
        const uint32_t Vd = shb + (uint32_t)((2 + buf) * FT) * 4u;
#pragma unroll
        for (int i = 0; i < 8; i++) {
            const int m = r0 + i*8;
            cpasync16(Kd + (uint32_t)(m*FSTR + (c4 ^ (m & 4))) * 4u,
                      Kg + (size_t)(kb*64 + i*8) * QKVS);
            cpasync16(Vd + (uint32_t)(m*FSTR + c4) * 4u,
                      Vg + (size_t)(kb*64 + i*8) * QKVS);
        }
    };

    // kick off KV(0) first so it overlaps the Q prologue
    stageKV(0, 0);
    CP_COMMIT();

    uint32_t qf[8][4];
    {
        const float* Qg = g_qkv + ((size_t)(b*CS + qb*64 + r0)) * QKVS + h*64 + c4;
#pragma unroll
        for (int i = 0; i < 8; i++) {
            const int m = r0 + i*8;
            *reinterpret_cast<float4*>(&Ps[m*FSTR + (c4 ^ (m & 4))]) =
                *reinterpret_cast<const float4*>(Qg + (size_t)(i*8) * QKVS);
        }
        __syncthreads();
#pragma unroll
        for (int k8 = 0; k8 < 8; k8++) {
            const int kk = k8*8;
            qf[k8][0] = Ps[rq*FSTR     + ((kk + tig)     ^ swa)];
            qf[k8][1] = Ps[(rq+8)*FSTR + ((kk + tig)     ^ swa)];
            qf[k8][2] = Ps[rq*FSTR     + ((kk + tig + 4) ^ swa)];
            qf[k8][3] = Ps[(rq+8)*FSTR + ((kk + tig + 4) ^ swa)];
        }
    }

    float accO[8][4] = {};
    float mrow[2] = {-1e30f, -1e30f};
    float lrow[2] = {0.f, 0.f};

    for (int kb = 0; kb <= qb; kb++) {
        const int cur = kb & 1;
        CP_WAIT(0);
        __syncthreads();
        if (kb < qb) {
            stageKV(1 - cur, kb + 1);
            CP_COMMIT();
        }

        const uint32_t* Ks = fsh + cur * FT;
        const uint32_t* Vs = fsh + (2 + cur) * FT;

        float accS[8][4] = {};
#pragma unroll
        for (int k8 = 0; k8 < 8; k8++) {
            const int kk = k8*8;
#pragma unroll
            for (int nt = 0; nt < 8; nt++) {
                const int n  = nt*8 + g;
                const int sw = n & 4;
                uint32_t bf[2];
                bf[0] = Ks[n*FSTR + ((kk + tig)     ^ sw)];
                bf[1] = Ks[n*FSTR + ((kk + tig + 4) ^ sw)];
                mma_tf32(accS[nt], qf[k8], bf);
            }
        }

        const float scale = 0.125f;
#pragma unroll
        for (int nt = 0; nt < 8; nt++) {
#pragma unroll
            for (int e = 0; e < 4; e++) accS[nt][e] *= scale;
            if (kb == qb) {
                const int col = nt*8 + 2*tig;
                if (col     > rq)   accS[nt][0] = -1e30f;
                if (col + 1 > rq)   accS[nt][1] = -1e30f;
                if (col     > rq+8) accS[nt][2] = -1e30f;
                if (col + 1 > rq+8) accS[nt][3] = -1e30f;
            }
        }

        float mn0 = mrow[0], mn1 = mrow[1];
#pragma unroll
        for (int nt = 0; nt < 8; nt++) {
            mn0 = fmaxf(mn0, fmaxf(accS[nt][0], accS[nt][1]));
            mn1 = fmaxf(mn1, fmaxf(accS[nt][2], accS[nt][3]));
        }
#pragma unroll
        for (int o = 1; o <= 2; o <<= 1) {
            mn0 = fmaxf(mn0, __shfl_xor_sync(0xffffffffu, mn0, o));
            mn1 = fmaxf(mn1, __shfl_xor_sync(0xffffffffu, mn1, o));
        }
        const float fac0 = __expf(mrow[0] - mn0);
        const float fac1 = __expf(mrow[1] - mn1);
        mrow[0] = mn0; mrow[1] = mn1;
        lrow[0] *= fac0; lrow[1] *= fac1;

        float ps0 = 0.f, ps1 = 0.f;
#pragma unroll
        for (int nt = 0; nt < 8; nt++) {
            uint32_t p0 = f2tf(__expf(accS[nt][0] - mn0));
            uint32_t p1 = f2tf(__expf(accS[nt][1] - mn0));
            uint32_t p2 = f2tf(__expf(accS[nt][2] - mn1));
            uint32_t p3 = f2tf(__expf(accS[nt][3] - mn1));
            ps0 += __uint_as_float(p0) + __uint_as_float(p1);
            ps1 += __uint_as_float(p2) + __uint_as_float(p3);
            const int col = (2*tig) ^ swa;
            *reinterpret_cast<uint2*>(&Ps[rq*FSTR     + nt*8 + col]) = make_uint2(p0, p1);
            *reinterpret_cast<uint2*>(&Ps[(rq+8)*FSTR + nt*8 + col]) = make_uint2(p2, p3);
            accO[nt][0] *= fac0; accO[nt][1] *= fac0;
            accO[nt][2] *= fac1; accO[nt][3] *= fac1;
        }
#pragma unroll
        for (int o = 1; o <= 2; o <<= 1) {
            ps0 += __shfl_xor_sync(0xffffffffu, ps0, o);
            ps1 += __shfl_xor_sync(0xffffffffu, ps1, o);
        }
        lrow[0] += ps0; lrow[1] += ps1;
        __syncwarp();

#pragma unroll
        for (int k8 = 0; k8 < 8; k8++) {
            const int kk = k8*8;
            uint32_t af[4];
            af[0] = Ps[rq*FSTR     + ((kk + tig)     ^ swa)];
            af[1] = Ps[(rq+8)*FSTR + ((kk + tig)     ^ swa)];
            af[2] = Ps[rq*FSTR     + ((kk + tig + 4) ^ swa)];
            af[3] = Ps[(rq+8)*FSTR + ((kk + tig + 4) ^ swa)];
#pragma unroll
            for (int nt = 0; nt < 8; nt++) {
                const int n = nt*8 + g;
                uint32_t bf[2];
                bf[0] = Vs[(kk + tig)     * FSTR + n];
                bf[1] = Vs[(kk + tig + 4) * FSTR + n];
                mma_tf32(accO[nt], af, bf);
            }
        }
    }

    // ---- normalize; store tf32-rounded, PERMUTED-K (feeds Wo GEMM as A) ----
    const float inv0 = 1.0f / lrow[0];
    const float inv1 = 1.0f / lrow[1];
    float* Og = g_at + ((size_t)(b*CS + qb*64 + rq)) * CD + h*64;
#pragma unroll
    for (int nt = 0; nt < 8; nt++) {
        const int c0 = nt*8 + 2*tig;
        const int c1 = c0 + 1;
        const int p0 = (c0 & ~31) | ((c0 & 3)*8 + ((c0 >> 2) & 7));
        const int p1 = (c1 & ~31) | ((c1 & 3)*8 + ((c1 >> 2) & 7));
        Og[p0] = rnd(accO[nt][0]*inv0);
        Og[p1] = rnd(accO[nt][1]*inv0);
        Og[(size_t)8*CD + p0] = rnd(accO[nt][2]*inv1);
        Og[(size_t)8*CD + p1] = rnd(accO[nt][3]*inv1);
    }
}

// ---------------- launch -----------------------------------------------------
extern "C" void kernel_launch(void* const* d_in, const int* in_sizes, int n_in,
                              void* d_out, int out_size) {
    const float* x    = (const float*)d_in[0];
    const float* pe   = (const float*)d_in[1];
    const float* ln1g = (const float*)d_in[3];
    const float* ln1b = (const float*)d_in[4];
    const float* wq   = (const float*)d_in[5];
    const float* wk   = (const float*)d_in[6];
    const float* wv   = (const float*)d_in[7];
    const float* wo   = (const float*)d_in[8];
    const float* ln2g = (const float*)d_in[9];
    const float* ln2b = (const float*)d_in[10];
    const float* wf   = (const float*)d_in[11];
    const float* lnfg = (const float*)d_in[12];
    const float* lnfb = (const float*)d_in[13];
    const float* wout = (const float*)d_in[14];

    float *ph, *phn, *pqkv, *pat, *pwc;
    cudaGetSymbolAddress((void**)&ph,   g_h);
    cudaGetSymbolAddress((void**)&phn,  g_hn);
    cudaGetSymbolAddress((void**)&pqkv, g_qkv);
    cudaGetSymbolAddress((void**)&pat,  g_at);
    cudaGetSymbolAddress((void**)&pwc,  g_wc);

    const size_t WSZ = (size_t)CL * CD * CD;
    float* cwqkv = pwc;
    float* cwo   = pwc + 3*WSZ;
    float* cwf   = pwc + 4*WSZ;
    float* cwout = pwc + 5*WSZ;

    const int gemmSmem  = 4 * NBUF * (int)sizeof(uint32_t);   // 73728 B
    const int flashSmem = 5 * FT   * (int)sizeof(uint32_t);   // 92160 B
    cudaFuncSetAttribute(k_gemm_tc, cudaFuncAttributeMaxDynamicSharedMemorySize, gemmSmem);
    cudaFuncSetAttribute(k_flash,   cudaFuncAttributeMaxDynamicSharedMemorySize, flashSmem);

    const int gW = (int)(WSZ / 4 / 256);
    k_cvtw3<<<dim3(gW, 3), 256>>>(wq, wk, wv, cwqkv);
    k_cvtw<<<gW, 256>>>(wo, cwo);
    k_cvtw<<<gW, 256>>>(wf, cwf);
    k_cvtw<<<(COUT*CD/4)/256, 256>>>(wout, cwout);

    k_addpe<<<(CM * CD / 4) / 256, 256>>>(x, pe);

    const dim3 gQKV(QKVS / 128, CM / 128);   // (24, 32)
    const dim3 gProj(CD / 128, CM / 128);    // (8, 32)
    const dim3 gOut (COUT / 128, CM / 128);  // (4, 32)
    const dim3 gFl  (CS / 64, CB * CH);

    for (int l = 0; l < CL; l++) {
        const size_t od   = (size_t)l * CD;
        const size_t odd  = (size_t)l * CD * CD;
        const size_t odd3 = (size_t)l * 3 * CD * CD;
        k_ln<<<CM, 256>>>(ph, phn, ln1g + od, ln1b + od);
        k_gemm_tc<<<gQKV, 256, gemmSmem>>>(phn, cwqkv + odd3, nullptr, pqkv, QKVS, CD, 0, 1);
        k_flash<<<gFl, 128, flashSmem>>>();
        k_gemm_tc<<<gProj, 256, gemmSmem>>>(pat, cwo + odd, ph, ph, CD, CD, 1, 0);
        k_ln<<<CM, 256>>>(ph, phn, ln2g + od, ln2b + od);
        k_gemm_tc<<<gProj, 256, gemmSmem>>>(phn, cwf + odd, ph, ph, CD, CD, 1, 0);
    }
    k_ln<<<CM, 256>>>(ph, phn, lnfg, lnfb);
    k_gemm_tc<<<gOut, 256, gemmSmem>>>(phn, cwout, nullptr, (float*)d_out, COUT, CD, 0, 0);
}